// round 13
// baseline (speedup 1.0000x reference)
#include <cuda_runtime.h>
#include <math.h>
#include <stdint.h>

// Problem constants
#define BB   64
#define NN   4096
#define IND  256
#define SS   8
#define DD   256
#define ROWS (BB*SS)        // 512
#define NG   32             // attention groups (blocks.y)
#define TN   32             // n's per tile
#define NTILE 4             // tiles per block (NG*NTILE*TN = 4096)

// -------- scratch (device globals; no allocation allowed) --------
__device__ float g_slots [ROWS*DD];
__device__ float g_qW    [ROWS*IND];
__device__ float g_upart [NG*ROWS*IND];   // unnormalized U partials (16 MB)
__device__ float g_m     [NG*ROWS];
__device__ float g_l     [NG*ROWS];
__device__ float g_wqk   [DD*IND];        // (Wq^T @ Wk)/16
__device__ float g_bqk   [IND];           // (bq @ Wk)/16
__device__ float g_wf    [3*DD*DD];       // W_ih @ Wv
__device__ float g_bf    [3*DD];          // W_ih @ bv + b_ih

// -------- reductions --------
__device__ __forceinline__ float warpSum(float v){
#pragma unroll
    for (int o = 16; o > 0; o >>= 1) v += __shfl_xor_sync(0xffffffffu, v, o);
    return v;
}
__device__ __forceinline__ float warpMax(float v){
#pragma unroll
    for (int o = 16; o > 0; o >>= 1) v = fmaxf(v, __shfl_xor_sync(0xffffffffu, v, o));
    return v;
}

// -------- slots = mu + sigma * noise --------
__global__ void init_slots_kernel(const float* __restrict__ noise,
                                  const float* __restrict__ mu,
                                  const float* __restrict__ sigma,
                                  float* __restrict__ slots){
    int i  = blockIdx.x * 256 + threadIdx.x;
    int sd = i & (SS*DD - 1);
    slots[i] = mu[sd] + sigma[sd] * noise[i];
}

// ============ one-off weight fusions ============
// blocks 0..15 : wqk[d][e] = (sum_c Wq[c][d]*Wk[c][e]) / 16        (256x256)
// blocks 16..63: wf[o][e]  =  sum_d W_ih[o][d]*Wv[d][e]            (768x256)
__global__ __launch_bounds__(256) void fuse_gemm_kernel(
        const float* __restrict__ Wq,   const float* __restrict__ Wk,
        const float* __restrict__ W_ih, const float* __restrict__ Wv,
        float* __restrict__ wqk, float* __restrict__ wf)
{
    __shared__ float As[32][65];
    __shared__ float Bs[32][65];
    int b = blockIdx.x, t = threadIdx.x;
    int tx = t & 15, ty = t >> 4;
    int mode = (b >= 16);
    const float *A, *Bm; float* C; int m0, n0;
    if (!mode){ A = Wq;   Bm = Wk; C = wqk; m0 = (b>>2)*64;        n0 = (b&3)*64; }
    else      { int bb=b-16; A = W_ih; Bm = Wv; C = wf; m0 = (bb>>2)*64; n0 = (bb&3)*64; }

    float acc[4][4] = {};
    for (int k0 = 0; k0 < 256; k0 += 32){
        if (!mode){
            // As[kk][mm] = Wq[(k0+kk)*256 + m0+mm]
#pragma unroll
            for (int p = 0; p < 8; ++p){
                int idx = t + p*256;
                int kk = idx >> 6, mm = idx & 63;
                As[kk][mm] = A[(size_t)(k0+kk)*256 + m0 + mm];
            }
        } else {
            // As[kk=dd][mm=oo] = W_ih[(m0+oo)*256 + k0+dd]
#pragma unroll
            for (int p = 0; p < 8; ++p){
                int idx = t + p*256;
                int oo = idx >> 5, dd = idx & 31;
                As[dd][oo] = A[(size_t)(m0+oo)*256 + k0 + dd];
            }
        }
#pragma unroll
        for (int p = 0; p < 8; ++p){
            int idx = t + p*256;
            int kk = idx >> 6, nn = idx & 63;
            Bs[kk][nn] = Bm[(size_t)(k0+kk)*256 + n0 + nn];
        }
        __syncthreads();
#pragma unroll
        for (int kk = 0; kk < 32; ++kk){
            float av[4], bw[4];
#pragma unroll
            for (int i = 0; i < 4; ++i){ av[i] = As[kk][ty*4+i]; bw[i] = Bs[kk][tx*4+i]; }
#pragma unroll
            for (int i = 0; i < 4; ++i)
#pragma unroll
                for (int j = 0; j < 4; ++j) acc[i][j] += av[i]*bw[j];
        }
        __syncthreads();
    }
    float sc = mode ? 1.f : 0.0625f;
#pragma unroll
    for (int i = 0; i < 4; ++i)
#pragma unroll
        for (int j = 0; j < 4; ++j)
            C[(size_t)(m0 + ty*4 + i)*256 + n0 + tx*4 + j] = acc[i][j]*sc;
}

// block 0: bqk[e] = (sum_c bq[c]*Wk[c][e]) / 16 ; blocks 1-3: bf[o] = W_ih[o].bv + b_ih[o]
__global__ __launch_bounds__(256) void fuse_bias_kernel(
        const float* __restrict__ bq,   const float* __restrict__ Wk,
        const float* __restrict__ W_ih, const float* __restrict__ bv,
        const float* __restrict__ b_ih,
        float* __restrict__ bqk, float* __restrict__ bf)
{
    int b = blockIdx.x, t = threadIdx.x;
    if (b == 0){
        float a = 0.f;
#pragma unroll 8
        for (int c = 0; c < 256; ++c) a += bq[c]*__ldg(&Wk[(size_t)c*256 + t]);
        bqk[t] = a * 0.0625f;
    } else {
        int o = (b-1)*256 + t;
        const float4* row = reinterpret_cast<const float4*>(W_ih + (size_t)o*256);
        const float4* vv  = reinterpret_cast<const float4*>(bv);
        float a = 0.f;
#pragma unroll 8
        for (int k4 = 0; k4 < 64; ++k4){
            float4 wv = __ldg(&row[k4]);
            float4 bw = __ldg(&vv[k4]);
            a += wv.x*bw.x + wv.y*bw.y + wv.z*bw.z + wv.w*bw.w;
        }
        bf[o] = a + b_ih[o];
    }
}

// Block LayerNorm (256-thread data path; callable from 256 OR 512 threads).
__device__ __forceinline__ void block_ln4(const float v[4], float o[4],
                                          const float* __restrict__ g,
                                          const float* __restrict__ b, int t)
{
    __shared__ float part[8][4];
    __shared__ float stat[4];
    int w = t >> 5, l = t & 31;
#pragma unroll
    for (int r = 0; r < 4; ++r){
        float p = warpSum(v[r]);
        if (l == 0 && w < 8) part[w][r] = p;
    }
    __syncthreads();
    if (t < 32){
        int rr = l >> 3, ww = l & 7;
        float x = part[ww][rr];
        x += __shfl_xor_sync(0xffffffffu, x, 1);
        x += __shfl_xor_sync(0xffffffffu, x, 2);
        x += __shfl_xor_sync(0xffffffffu, x, 4);
        if (ww == 0) stat[rr] = x * (1.f/256.f);
    }
    __syncthreads();
    float d[4];
#pragma unroll
    for (int r = 0; r < 4; ++r) d[r] = v[r] - stat[r];
    __syncthreads();
#pragma unroll
    for (int r = 0; r < 4; ++r){
        float p = warpSum(d[r]*d[r]);
        if (l == 0 && w < 8) part[w][r] = p;
    }
    __syncthreads();
    if (t < 32){
        int rr = l >> 3, ww = l & 7;
        float x = part[ww][rr];
        x += __shfl_xor_sync(0xffffffffu, x, 1);
        x += __shfl_xor_sync(0xffffffffu, x, 2);
        x += __shfl_xor_sync(0xffffffffu, x, 4);
        if (ww == 0) stat[rr] = rsqrtf(x * (1.f/256.f) + 1e-5f);
    }
    __syncthreads();
    int tc = t & 255;
    float gg = g[tc], bb = b[tc];
#pragma unroll
    for (int r = 0; r < 4; ++r) o[r] = d[r] * stat[r] * gg + bb;
}

// ============ gemm_tiles v2: row-major staging (STS.128 in, LDS.128 out) ============
__device__ __forceinline__ void gemm_tiles(
        const float (*sA)[DD],
        const float* __restrict__ W,
        float* __restrict__ sWt,     // this group's staging [256][36]
        float acc[4], int tc, int ktStart, int ktCount)
{
    const float4* Wp = reinterpret_cast<const float4*>(W);
    float4 r[8];
#pragma unroll
    for (int p = 0; p < 8; ++p){
        int idx = tc + p*256;
        r[p] = __ldg(&Wp[(size_t)(idx >> 3)*64 + ktStart*8 + (idx & 7)]);
    }
    acc[0] = acc[1] = acc[2] = acc[3] = 0.f;

    for (int kt = 0; kt < ktCount; ++kt){
        __syncthreads();
#pragma unroll
        for (int p = 0; p < 8; ++p){
            int idx = tc + p*256;
            *reinterpret_cast<float4*>(&sWt[(idx >> 3)*36 + (idx & 7)*4]) = r[p];
        }
        __syncthreads();
        if (kt + 1 < ktCount){
#pragma unroll
            for (int p = 0; p < 8; ++p){
                int idx = tc + p*256;
                r[p] = __ldg(&Wp[(size_t)(idx >> 3)*64 + (ktStart+kt+1)*8 + (idx & 7)]);
            }
        }
        int kb = (ktStart + kt)*32;
#pragma unroll
        for (int kk4 = 0; kk4 < 8; ++kk4){
            float4 a0 = *(const float4*)&sA[0][kb + kk4*4];
            float4 a1 = *(const float4*)&sA[1][kb + kk4*4];
            float4 a2 = *(const float4*)&sA[2][kb + kk4*4];
            float4 a3 = *(const float4*)&sA[3][kb + kk4*4];
            float4 wv = *(const float4*)&sWt[tc*36 + kk4*4];
            acc[0] += a0.x*wv.x + a0.y*wv.y + a0.z*wv.z + a0.w*wv.w;
            acc[1] += a1.x*wv.x + a1.y*wv.y + a1.z*wv.z + a1.w*wv.w;
            acc[2] += a2.x*wv.x + a2.y*wv.y + a2.z*wv.z + a2.w*wv.w;
            acc[3] += a3.x*wv.x + a3.y*wv.y + a3.z*wv.z + a3.w*wv.w;
        }
    }
}

// ============ PRE, 512 threads: LN -> qW = LN @ wqk + bqk (fused, split-K stream) ====
__global__ __launch_bounds__(512) void pre_kernel(
        const float* __restrict__ slots,
        const float* __restrict__ lng, const float* __restrict__ lnb,
        const float* __restrict__ wqk, const float* __restrict__ bqk,
        float* __restrict__ qW)
{
    __shared__ float s_ln[4][DD];
    __shared__ float sPar[4][DD];

    int r0 = blockIdx.x * 4;
    int t  = threadIdx.x;
    int tc = t & 255, grp = t >> 8;

    float v[4] = {0.f, 0.f, 0.f, 0.f};
    if (grp == 0){
#pragma unroll
        for (int r = 0; r < 4; ++r) v[r] = slots[(size_t)(r0+r)*DD + tc];
    }
    float o[4];
    block_ln4(v, o, lng, lnb, t);
    if (grp == 0){
#pragma unroll
        for (int r = 0; r < 4; ++r) s_ln[r][tc] = o[r];
    }
    __syncthreads();

    float c0=0.f, c1=0.f, c2=0.f, c3=0.f;
    int d0 = grp*128;
#pragma unroll 8
    for (int d = d0; d < d0 + 128; ++d){
        float wv = __ldg(&wqk[(size_t)d*IND + tc]);
        c0 += s_ln[0][d]*wv; c1 += s_ln[1][d]*wv;
        c2 += s_ln[2][d]*wv; c3 += s_ln[3][d]*wv;
    }
    if (grp == 1){
        sPar[0][tc] = c0; sPar[1][tc] = c1;
        sPar[2][tc] = c2; sPar[3][tc] = c3;
    }
    __syncthreads();
    if (grp == 0){
        float bb = __ldg(&bqk[tc]);
        qW[(size_t)(r0+0)*IND + tc] = c0 + sPar[0][tc] + bb;
        qW[(size_t)(r0+1)*IND + tc] = c1 + sPar[1][tc] + bb;
        qW[(size_t)(r0+2)*IND + tc] = c2 + sPar[2][tc] + bb;
        qW[(size_t)(r0+3)*IND + tc] = c3 + sPar[3][tc] + bb;
    }
}

// ============ FLASH attention, TN=32 tiles, NG=32 (6.9 waves), 2 blocks/SM ==========
__global__ __launch_bounds__(512, 2) void attn_kernel(
        const float* __restrict__ qW,
        const float* __restrict__ inputs,
        float* __restrict__ upart,
        float* __restrict__ mbuf,
        float* __restrict__ lbuf)
{
    extern __shared__ float dsm[];
    float* Xs  = dsm;                  // 2 * 8192 floats (64 KB)
    float* qT  = dsm + 16384;          // [k][s] 2048
    float* lgp = qT  + 2048;           // [ks][s][n] 16*8*32 = 4096
    float* atT = lgp + 4096;           // [n][12] 384
    float* scs = atT + 384;            // 8

    int b = blockIdx.x, g = blockIdx.y;
    int t = threadIdx.x, w = t >> 5, l = t & 31;

    // stage qT
#pragma unroll
    for (int p = 0; p < 4; ++p){
        int idx = t + p*512;
        qT[(idx & 255)*8 + (idx >> 8)] = qW[(size_t)b*2048 + idx];
    }

    const float* src0 = inputs + ((size_t)b*NN + g*(NTILE*TN))*IND;
#define PREFETCH(j, buf) do {                                                   \
        const float* _s = src0 + (size_t)(j)*TN*IND;                            \
        float* _d = Xs + (buf)*8192;                                            \
        _Pragma("unroll")                                                       \
        for (int p = 0; p < 4; ++p){                                            \
            int idx = t + p*512;                                                \
            int n = idx >> 6, k4 = idx & 63;                                    \
            uint32_t sa = (uint32_t)__cvta_generic_to_shared(                   \
                              &_d[(n*64 + (k4 ^ (n & 7)))*4]);                  \
            asm volatile("cp.async.cg.shared.global [%0], [%1], 16;"            \
                         :: "r"(sa), "l"(_s + (size_t)n*IND + k4*4) : "memory");\
        }                                                                       \
        asm volatile("cp.async.commit_group;" ::: "memory");                    \
    } while(0)

    PREFETCH(0, 0);

    float m_run = -3.4e38f, lpart = 0.f;
    float uacc[4] = {};
    const int sh = (t >= 256) ? 4 : 0;     // phase3 slot-half
    const int e  = t & 255;
    const int e4 = e >> 2, eo = e & 3;
    const int ks = t >> 5;                 // phase1 k-slice (= warp id)
    const int pn = t & 31;                 // phase1 n (= lane)

    // ---- hoisted swizzle address math ----
    const int c  = pn & 7;
    const int p1base = pn*256 + ((ks*4) ^ (c & 4))*4;
    int a1[4];
#pragma unroll
    for (int i = 0; i < 4; ++i) a1[i] = p1base + (i ^ (c & 3))*4;
    int off3[8];
#pragma unroll
    for (int cc = 0; cc < 8; ++cc) off3[cc] = (e4 ^ cc)*4 + eo;

    for (int j = 0; j < NTILE; ++j){
        int buf = j & 1;
        asm volatile("cp.async.wait_group 0;" ::: "memory");
        __syncthreads();                                   // S1: tile ready, prior reads done
        if (j + 1 < NTILE) PREFETCH(j + 1, buf ^ 1);
        const float* Xb = Xs + buf*8192;

        // ---- phase 1: logits partials; warp = k-slice (16 k), lane = n ----
        {
            float acc[8] = {};
#pragma unroll
            for (int i = 0; i < 4; ++i){
                float4 x4 = *(const float4*)&Xb[a1[i]];
                int k = (ks*4 + i)*4;
                float xv[4] = {x4.x, x4.y, x4.z, x4.w};
#pragma unroll
                for (int d = 0; d < 4; ++d){
                    float4 qa = *(const float4*)&qT[(k+d)*8];
                    float4 qb = *(const float4*)&qT[(k+d)*8 + 4];
                    acc[0] += xv[d]*qa.x; acc[1] += xv[d]*qa.y;
                    acc[2] += xv[d]*qa.z; acc[3] += xv[d]*qa.w;
                    acc[4] += xv[d]*qb.x; acc[5] += xv[d]*qb.y;
                    acc[6] += xv[d]*qb.z; acc[7] += xv[d]*qb.w;
                }
            }
#pragma unroll
            for (int s = 0; s < 8; ++s) lgp[ks*256 + s*32 + pn] = acc[s];
        }
        __syncthreads();                                   // S2: lgp ready

        // ---- phase 2: online softmax; warp w<8 owns slot w, lane = key ----
        if (w < 8){
            float lg = 0.f;
#pragma unroll
            for (int kq = 0; kq < 16; ++kq) lg += lgp[kq*256 + w*32 + l];
            float mv = warpMax(lg);
            float m_new = fmaxf(m_run, mv);
            float ev = __expf(lg - m_new);
            atT[l*12 + w] = ev;
            float sc = __expf(m_run - m_new);
            lpart = lpart*sc + ev;
            m_run = m_new;
            if (l == 0) scs[w] = sc;
        }
        __syncthreads();                                   // S3: atT/scs ready

        // ---- phase 3: U accumulation; halves own slots sh..sh+3, col e ----
        {
            float4 sv = *(const float4*)&scs[sh];
            uacc[0] *= sv.x; uacc[1] *= sv.y; uacc[2] *= sv.z; uacc[3] *= sv.w;
            for (int n8 = 0; n8 < TN; n8 += 8){
#pragma unroll
                for (int cc = 0; cc < 8; ++cc){
                    int n = n8 + cc;
                    float x = Xb[n*256 + off3[cc]];
                    float4 a = *(const float4*)&atT[n*12 + sh];
                    uacc[0] += a.x*x; uacc[1] += a.y*x;
                    uacc[2] += a.z*x; uacc[3] += a.w*x;
                }
            }
        }
    }
#undef PREFETCH

#pragma unroll
    for (int i = 0; i < 4; ++i)
        upart[((size_t)g*ROWS + b*SS + sh + i)*IND + e] = uacc[i];
    if (w < 8){
        float l_run = warpSum(lpart);
        if (l == 0){
            int row = b*SS + w;
            mbuf[(size_t)g*ROWS + row] = m_run;
            lbuf[(size_t)g*ROWS + row] = l_run;
        }
    }
}

// ============ POST, 512 threads: fused gi (Wf on U) + gh concurrent, then MLP ========
__global__ __launch_bounds__(512) void post_kernel(
        const float* __restrict__ upart,
        const float* __restrict__ mbuf, const float* __restrict__ lbuf,
        const float* __restrict__ wf,   const float* __restrict__ bf,
        const float* __restrict__ W_hh, const float* __restrict__ b_hh,
        const float* __restrict__ lng,  const float* __restrict__ lnb,
        const float* __restrict__ W1,   const float* __restrict__ b1,
        const float* __restrict__ W2,   const float* __restrict__ b2,
        const float* __restrict__ slots_in,
        float* __restrict__ dst)
{
    extern __shared__ float dsm[];
    float (*sBufA)[DD] = (float(*)[DD])(dsm);           // 1024  U / sln
    float (*sprev)[DD] = (float(*)[DD])(dsm + 1024);    // 1024
    float (*sBufB)[DD] = (float(*)[DD])(dsm + 2048);    // 1024  hidden
    float* sGh         = dsm + 3072;                    // 3072  gh[3][4][256]
    float (*sPar)[DD]  = (float(*)[DD])(dsm + 6144);    // 1024  split-k partials
    float* sWtA        = dsm + 7168;                    // 9216
    float* sWtB        = dsm + 16384;                   // 9216

    __shared__ float ssc[4][33];
    __shared__ float sinv[4];

    int r0 = blockIdx.x * 4;
    int t  = threadIdx.x;
    int tc = t & 255, grp = t >> 8;
    int w  = t >> 5, l = t & 31;
    float* myWt = grp ? sWtB : sWtA;

    // 1. per-row combine scales over NG=32 groups (warps 0-3, one lane per chunk)
    if (w < 4){
        int row = r0 + w;
        float mv = __ldg(&mbuf[(size_t)l*ROWS + row]);
        float mm = warpMax(mv);
        float e  = __expf(mv - mm);
        float lv = warpSum(__ldg(&lbuf[(size_t)l*ROWS + row]) * e);
        ssc[w][l] = e;
        if (l == 0) sinv[w] = 1.f / lv;
    }
    __syncthreads();

    // 2. U = (sum_g Ubar_g*sc_g)*inv ; load slots_prev (each thread 2 rows)
#pragma unroll
    for (int rr = 0; rr < 2; ++rr){
        int r = grp*2 + rr, row = r0 + r;
        float a = 0.f;
#pragma unroll
        for (int ch = 0; ch < NG; ++ch)
            a += __ldg(&upart[((size_t)ch*ROWS + row)*IND + tc]) * ssc[r][ch];
        sBufA[r][tc] = a * sinv[r];
        sprev[r][tc] = slots_in[(size_t)row*DD + tc];
    }
    // (first barrier inside gemm_tiles orders these writes)

    // 3. GRU gates concurrently: grp0 -> gi = U @ wf^T + bf ; grp1 -> gh on prev
    float acc[4];
    float gi[3][4];
#pragma unroll
    for (int j = 0; j < 3; ++j){
        const float* Wg = grp ? (W_hh + (size_t)j*DD*DD) : (wf + (size_t)j*DD*DD);
        const float (*Ag)[DD] = grp ? sprev : sBufA;
        gemm_tiles(Ag, Wg, myWt, acc, tc, 0, 8);
        if (grp == 0){
            float bb = __ldg(&bf[tc + j*256]);
#pragma unroll
            for (int r = 0; r < 4; ++r) gi[j][r] = acc[r] + bb;
        } else {
            float bb = __ldg(&b_hh[tc + j*256]);
#pragma unroll
            for (int r = 0; r < 4; ++r) sGh[(j*4 + r)*256 + tc] = acc[r] + bb;
        }
    }
    __syncthreads();

    // 4. GRU cell + residual (grp0)
    float vnew[4] = {0.f, 0.f, 0.f, 0.f};
    if (grp == 0){
#pragma unroll
        for (int r = 0; r < 4; ++r){
            float hr = sGh[(0*4 + r)*256 + tc];
            float hz = sGh[(1*4 + r)*256 + tc];
            float hn = sGh[(2*4 + r)*256 + tc];
            float rr = 1.f / (1.f + expf(-(gi[0][r] + hr)));
            float zz = 1.f / (1.f + expf(-(gi[1][r] + hz)));
            float nn = tanhf(gi[2][r] + rr*hn);
            float h  = sprev[r][tc];
            vnew[r]  = h + (1.f - zz)*nn + zz*h;
        }
    }

    // 5. LN(vnew) -> sBufA (grp0 data; all threads pass barriers)
    float lnv[4];
    block_ln4(vnew, lnv, lng, lnb, t);
    if (grp == 0){
#pragma unroll
        for (int r = 0; r < 4; ++r) sBufA[r][tc] = lnv[r];
    }

    // 6. hidden = relu(sln @ W1^T + b1) -> sBufB (split-K)
    gemm_tiles(sBufA, W1, myWt, acc, tc, grp*4, 4);
    if (grp == 1){
#pragma unroll
        for (int r = 0; r < 4; ++r) sPar[r][tc] = acc[r];
    }
    __syncthreads();
    if (grp == 0){
        float bb = __ldg(&b1[tc]);
#pragma unroll
        for (int r = 0; r < 4; ++r) sBufB[r][tc] = fmaxf(acc[r] + sPar[r][tc] + bb, 0.f);
    }

    // 7. out = vnew + hid @ W2^T + b2 (split-K)
    gemm_tiles(sBufB, W2, myWt, acc, tc, grp*4, 4);
    if (grp == 1){
#pragma unroll
        for (int r = 0; r < 4; ++r) sPar[r][tc] = acc[r];
    }
    __syncthreads();
    if (grp == 0){
        float bb = __ldg(&b2[tc]);
#pragma unroll
        for (int r = 0; r < 4; ++r)
            dst[(size_t)(r0+r)*DD + tc] = vnew[r] + acc[r] + sPar[r][tc] + bb;
    }
}

// ------------------------- host launcher -------------------------
extern "C" void kernel_launch(void* const* d_in, const int* in_sizes, int n_in,
                              void* d_out, int out_size)
{
    const float* inputs = (const float*)d_in[0];
    const float* noise  = (const float*)d_in[1];
    const float* s_mu   = (const float*)d_in[2];
    const float* s_sig  = (const float*)d_in[3];
    const float* Wq = (const float*)d_in[4];  const float* bq = (const float*)d_in[5];
    const float* Wk = (const float*)d_in[6];  /* bk = d_in[7] : dead (softmax shift-invariance) */
    const float* Wv = (const float*)d_in[8];  const float* bv = (const float*)d_in[9];
    const float* W_ih = (const float*)d_in[10]; const float* b_ih = (const float*)d_in[11];
    const float* W_hh = (const float*)d_in[12]; const float* b_hh = (const float*)d_in[13];
    const float* W1 = (const float*)d_in[14]; const float* b1 = (const float*)d_in[15];
    const float* W2 = (const float*)d_in[16]; const float* b2 = (const float*)d_in[17];
    const float* lnsg = (const float*)d_in[18]; const float* lnsb = (const float*)d_in[19];
    const float* lnmg = (const float*)d_in[20]; const float* lnmb = (const float*)d_in[21];
    float* out = (float*)d_out;
    (void)in_sizes; (void)n_in; (void)out_size;

    float *slots, *qW, *upart, *mbuf, *lbuf, *wqk, *bqk, *wf, *bf;
    cudaGetSymbolAddress((void**)&slots, g_slots);
    cudaGetSymbolAddress((void**)&qW,    g_qW);
    cudaGetSymbolAddress((void**)&upart, g_upart);
    cudaGetSymbolAddress((void**)&mbuf,  g_m);
    cudaGetSymbolAddress((void**)&lbuf,  g_l);
    cudaGetSymbolAddress((void**)&wqk,   g_wqk);
    cudaGetSymbolAddress((void**)&bqk,   g_bqk);
    cudaGetSymbolAddress((void**)&wf,    g_wf);
    cudaGetSymbolAddress((void**)&bf,    g_bf);

    const int ATTN_SMEM = (16384 + 2048 + 4096 + 384 + 8) * 4;   // 91,680 B -> 2 blocks/SM
    const int POST_SMEM = (7168 + 9216*2) * 4;                   // 102,400 B
    static int s_init = 0;
    if (!s_init){
        cudaFuncSetAttribute(attn_kernel, cudaFuncAttributeMaxDynamicSharedMemorySize, ATTN_SMEM);
        cudaFuncSetAttribute(post_kernel, cudaFuncAttributeMaxDynamicSharedMemorySize, POST_SMEM);
        s_init = 1;
    }

    dim3 gBN(BB, NG);

    init_slots_kernel<<<ROWS, 256>>>(noise, s_mu, s_sig, slots);
    fuse_gemm_kernel<<<64, 256>>>(Wq, Wk, W_ih, Wv, wqk, wf);
    fuse_bias_kernel<<<4, 256>>>(bq, Wk, W_ih, bv, b_ih, bqk, bf);

    for (int it = 0; it < 3; ++it){
        pre_kernel<<<ROWS/4, 512>>>(slots, lnsg, lnsb, wqk, bqk, qW);
        attn_kernel<<<gBN, 512, ATTN_SMEM>>>(qW, inputs, upart, mbuf, lbuf);
        float* dst = (it == 2) ? out : slots;
        post_kernel<<<ROWS/4, 512, POST_SMEM>>>(upart, mbuf, lbuf, wf, bf, W_hh, b_hh,
                                                lnmg, lnmb, W1, b1, W2, b2, slots, dst);
    }
}

// round 14
// speedup vs baseline: 1.0480x; 1.0480x over previous
#include <cuda_runtime.h>
#include <math.h>
#include <stdint.h>

// Problem constants
#define BB   64
#define NN   4096
#define IND  256
#define SS   8
#define DD   256
#define ROWS (BB*SS)        // 512
#define NG   16             // attention groups (blocks.y)
#define TN   32             // n's per tile
#define NTILE 8             // tiles per block (NG*NTILE*TN = 4096)

// -------- scratch (device globals; no allocation allowed) --------
__device__ float g_slots [ROWS*DD];
__device__ float g_qW    [ROWS*IND];
__device__ float g_upart [NG*ROWS*IND];   // unnormalized U partials (8 MB)
__device__ float g_m     [NG*ROWS];
__device__ float g_l     [NG*ROWS];
__device__ float g_wqkT  [IND*DD];        // ((Wq^T @ Wk)/16)^T : [e][d]
__device__ float g_bqk   [IND];           // (bq @ Wk)/16
__device__ float g_wf    [3*DD*DD];       // W_ih @ Wv  (row = gate output o, col = e)
__device__ float g_bf    [3*DD];          // W_ih @ bv + b_ih

// -------- reductions --------
__device__ __forceinline__ float warpSum(float v){
#pragma unroll
    for (int o = 16; o > 0; o >>= 1) v += __shfl_xor_sync(0xffffffffu, v, o);
    return v;
}
__device__ __forceinline__ float warpMax(float v){
#pragma unroll
    for (int o = 16; o > 0; o >>= 1) v = fmaxf(v, __shfl_xor_sync(0xffffffffu, v, o));
    return v;
}

// -------- slots = mu + sigma * noise --------
__global__ void init_slots_kernel(const float* __restrict__ noise,
                                  const float* __restrict__ mu,
                                  const float* __restrict__ sigma,
                                  float* __restrict__ slots){
    int i  = blockIdx.x * 256 + threadIdx.x;
    int sd = i & (SS*DD - 1);
    slots[i] = mu[sd] + sigma[sd] * noise[i];
}

// ============ one-off weight fusions ============
// blocks 0..15 : wqkT[e][d] = (sum_c Wq[c][d]*Wk[c][e]) / 16   (stored TRANSPOSED)
// blocks 16..63: wf[o][e]   =  sum_d W_ih[o][d]*Wv[d][e]       (768x256, row-major)
__global__ __launch_bounds__(256) void fuse_gemm_kernel(
        const float* __restrict__ Wq,   const float* __restrict__ Wk,
        const float* __restrict__ W_ih, const float* __restrict__ Wv,
        float* __restrict__ wqkT, float* __restrict__ wf)
{
    __shared__ float As[32][65];
    __shared__ float Bs[32][65];
    int b = blockIdx.x, t = threadIdx.x;
    int tx = t & 15, ty = t >> 4;
    int mode = (b >= 16);
    const float *A, *Bm; int m0, n0;
    if (!mode){ A = Wq;   Bm = Wk; m0 = (b>>2)*64;         n0 = (b&3)*64; }
    else      { int bb=b-16; A = W_ih; Bm = Wv; m0 = (bb>>2)*64; n0 = (bb&3)*64; }

    float acc[4][4] = {};
    for (int k0 = 0; k0 < 256; k0 += 32){
        if (!mode){
#pragma unroll
            for (int p = 0; p < 8; ++p){
                int idx = t + p*256;
                int kk = idx >> 6, mm = idx & 63;
                As[kk][mm] = A[(size_t)(k0+kk)*256 + m0 + mm];
            }
        } else {
#pragma unroll
            for (int p = 0; p < 8; ++p){
                int idx = t + p*256;
                int oo = idx >> 5, dd = idx & 31;
                As[dd][oo] = A[(size_t)(m0+oo)*256 + k0 + dd];
            }
        }
#pragma unroll
        for (int p = 0; p < 8; ++p){
            int idx = t + p*256;
            int kk = idx >> 6, nn = idx & 63;
            Bs[kk][nn] = Bm[(size_t)(k0+kk)*256 + n0 + nn];
        }
        __syncthreads();
#pragma unroll
        for (int kk = 0; kk < 32; ++kk){
            float av[4], bw[4];
#pragma unroll
            for (int i = 0; i < 4; ++i){ av[i] = As[kk][ty*4+i]; bw[i] = Bs[kk][tx*4+i]; }
#pragma unroll
            for (int i = 0; i < 4; ++i)
#pragma unroll
                for (int j = 0; j < 4; ++j) acc[i][j] += av[i]*bw[j];
        }
        __syncthreads();
    }
    if (!mode){
        // store TRANSPOSED: wqkT[e = n][d = m] = acc/16
#pragma unroll
        for (int i = 0; i < 4; ++i)
#pragma unroll
            for (int j = 0; j < 4; ++j)
                wqkT[(size_t)(n0 + tx*4 + j)*256 + m0 + ty*4 + i] = acc[i][j]*0.0625f;
    } else {
#pragma unroll
        for (int i = 0; i < 4; ++i)
#pragma unroll
            for (int j = 0; j < 4; ++j)
                wf[(size_t)(m0 + ty*4 + i)*256 + n0 + tx*4 + j] = acc[i][j];
    }
}

// block 0: bqk[e] = (sum_c bq[c]*Wk[c][e]) / 16 ; blocks 1-3: bf[o] = W_ih[o].bv + b_ih[o]
__global__ __launch_bounds__(256) void fuse_bias_kernel(
        const float* __restrict__ bq,   const float* __restrict__ Wk,
        const float* __restrict__ W_ih, const float* __restrict__ bv,
        const float* __restrict__ b_ih,
        float* __restrict__ bqk, float* __restrict__ bf)
{
    int b = blockIdx.x, t = threadIdx.x;
    if (b == 0){
        float a = 0.f;
#pragma unroll 8
        for (int c = 0; c < 256; ++c) a += bq[c]*__ldg(&Wk[(size_t)c*256 + t]);
        bqk[t] = a * 0.0625f;
    } else {
        int o = (b-1)*256 + t;
        const float4* row = reinterpret_cast<const float4*>(W_ih + (size_t)o*256);
        const float4* vv  = reinterpret_cast<const float4*>(bv);
        float a = 0.f;
#pragma unroll 8
        for (int k4 = 0; k4 < 64; ++k4){
            float4 wv = __ldg(&row[k4]);
            float4 bw = __ldg(&vv[k4]);
            a += wv.x*bw.x + wv.y*bw.y + wv.z*bw.z + wv.w*bw.w;
        }
        bf[o] = a + b_ih[o];
    }
}

// Block LayerNorm (256-thread data path; callable from 256 OR 512 threads).
__device__ __forceinline__ void block_ln4(const float v[4], float o[4],
                                          const float* __restrict__ g,
                                          const float* __restrict__ b, int t)
{
    __shared__ float part[8][4];
    __shared__ float stat[4];
    int w = t >> 5, l = t & 31;
#pragma unroll
    for (int r = 0; r < 4; ++r){
        float p = warpSum(v[r]);
        if (l == 0 && w < 8) part[w][r] = p;
    }
    __syncthreads();
    if (t < 32){
        int rr = l >> 3, ww = l & 7;
        float x = part[ww][rr];
        x += __shfl_xor_sync(0xffffffffu, x, 1);
        x += __shfl_xor_sync(0xffffffffu, x, 2);
        x += __shfl_xor_sync(0xffffffffu, x, 4);
        if (ww == 0) stat[rr] = x * (1.f/256.f);
    }
    __syncthreads();
    float d[4];
#pragma unroll
    for (int r = 0; r < 4; ++r) d[r] = v[r] - stat[r];
    __syncthreads();
#pragma unroll
    for (int r = 0; r < 4; ++r){
        float p = warpSum(d[r]*d[r]);
        if (l == 0 && w < 8) part[w][r] = p;
    }
    __syncthreads();
    if (t < 32){
        int rr = l >> 3, ww = l & 7;
        float x = part[ww][rr];
        x += __shfl_xor_sync(0xffffffffu, x, 1);
        x += __shfl_xor_sync(0xffffffffu, x, 2);
        x += __shfl_xor_sync(0xffffffffu, x, 4);
        if (ww == 0) stat[rr] = rsqrtf(x * (1.f/256.f) + 1e-5f);
    }
    __syncthreads();
    int tc = t & 255;
    float gg = g[tc], bb = b[tc];
#pragma unroll
    for (int r = 0; r < 4; ++r) o[r] = d[r] * stat[r] * gg + bb;
}

// ============ gemm_tiles v2: row-major staging (STS.128 in, LDS.128 out) ============
__device__ __forceinline__ void gemm_tiles(
        const float (*sA)[DD],
        const float* __restrict__ W,
        float* __restrict__ sWt,     // this group's staging [256][36]
        float acc[4], int tc, int ktStart, int ktCount)
{
    const float4* Wp = reinterpret_cast<const float4*>(W);
    float4 r[8];
#pragma unroll
    for (int p = 0; p < 8; ++p){
        int idx = tc + p*256;
        r[p] = __ldg(&Wp[(size_t)(idx >> 3)*64 + ktStart*8 + (idx & 7)]);
    }
    acc[0] = acc[1] = acc[2] = acc[3] = 0.f;

    for (int kt = 0; kt < ktCount; ++kt){
        __syncthreads();
#pragma unroll
        for (int p = 0; p < 8; ++p){
            int idx = tc + p*256;
            *reinterpret_cast<float4*>(&sWt[(idx >> 3)*36 + (idx & 7)*4]) = r[p];
        }
        __syncthreads();
        if (kt + 1 < ktCount){
#pragma unroll
            for (int p = 0; p < 8; ++p){
                int idx = tc + p*256;
                r[p] = __ldg(&Wp[(size_t)(idx >> 3)*64 + (ktStart+kt+1)*8 + (idx & 7)]);
            }
        }
        int kb = (ktStart + kt)*32;
#pragma unroll
        for (int kk4 = 0; kk4 < 8; ++kk4){
            float4 a0 = *(const float4*)&sA[0][kb + kk4*4];
            float4 a1 = *(const float4*)&sA[1][kb + kk4*4];
            float4 a2 = *(const float4*)&sA[2][kb + kk4*4];
            float4 a3 = *(const float4*)&sA[3][kb + kk4*4];
            float4 wv = *(const float4*)&sWt[tc*36 + kk4*4];
            acc[0] += a0.x*wv.x + a0.y*wv.y + a0.z*wv.z + a0.w*wv.w;
            acc[1] += a1.x*wv.x + a1.y*wv.y + a1.z*wv.z + a1.w*wv.w;
            acc[2] += a2.x*wv.x + a2.y*wv.y + a2.z*wv.z + a2.w*wv.w;
            acc[3] += a3.x*wv.x + a3.y*wv.y + a3.z*wv.z + a3.w*wv.w;
        }
    }
}

// ============ PRE, 512 threads: LN -> qW = LN @ wqkT^T + bqk via gemm_tiles ==========
__global__ __launch_bounds__(512) void pre_kernel(
        const float* __restrict__ slots,
        const float* __restrict__ lng, const float* __restrict__ lnb,
        const float* __restrict__ wqkT, const float* __restrict__ bqk,
        float* __restrict__ qW)
{
    extern __shared__ float dsm[];
    float (*s_ln)[DD] = (float(*)[DD])(dsm);            // 1024
    float (*sPar)[DD] = (float(*)[DD])(dsm + 1024);     // 1024
    float* sWtA       = dsm + 2048;                     // 9216
    float* sWtB       = dsm + 11264;                    // 9216

    int r0 = blockIdx.x * 4;
    int t  = threadIdx.x;
    int tc = t & 255, grp = t >> 8;
    float* myWt = grp ? sWtB : sWtA;

    float v[4] = {0.f, 0.f, 0.f, 0.f};
    if (grp == 0){
#pragma unroll
        for (int r = 0; r < 4; ++r) v[r] = slots[(size_t)(r0+r)*DD + tc];
    }
    float o[4];
    block_ln4(v, o, lng, lnb, t);
    if (grp == 0){
#pragma unroll
        for (int r = 0; r < 4; ++r) s_ln[r][tc] = o[r];
    }
    // (leading sync inside gemm_tiles orders s_ln writes)

    // qW[r][e=tc] = sum_d s_ln[r][d] * wqkT[e][d] + bqk[e]  (split-K)
    float acc[4];
    gemm_tiles(s_ln, wqkT, myWt, acc, tc, grp*4, 4);
    if (grp == 1){
#pragma unroll
        for (int r = 0; r < 4; ++r) sPar[r][tc] = acc[r];
    }
    __syncthreads();
    if (grp == 0){
        float bb = __ldg(&bqk[tc]);
        qW[(size_t)(r0+0)*IND + tc] = acc[0] + sPar[0][tc] + bb;
        qW[(size_t)(r0+1)*IND + tc] = acc[1] + sPar[1][tc] + bb;
        qW[(size_t)(r0+2)*IND + tc] = acc[2] + sPar[2][tc] + bb;
        qW[(size_t)(r0+3)*IND + tc] = acc[3] + sPar[3][tc] + bb;
    }
}

// ============ FLASH attention, TN=32 tiles, NG=16, 2 blocks/SM ============
__global__ __launch_bounds__(512, 2) void attn_kernel(
        const float* __restrict__ qW,
        const float* __restrict__ inputs,
        float* __restrict__ upart,
        float* __restrict__ mbuf,
        float* __restrict__ lbuf)
{
    extern __shared__ float dsm[];
    float* Xs  = dsm;                  // 2 * 8192 floats (64 KB)
    float* qT  = dsm + 16384;          // [k][s] 2048
    float* lgp = qT  + 2048;           // [ks][s][n] 16*8*32 = 4096
    float* atT = lgp + 4096;           // [n][12] 384
    float* scs = atT + 384;            // 8

    int b = blockIdx.x, g = blockIdx.y;
    int t = threadIdx.x, w = t >> 5, l = t & 31;

    // stage qT
#pragma unroll
    for (int p = 0; p < 4; ++p){
        int idx = t + p*512;
        qT[(idx & 255)*8 + (idx >> 8)] = qW[(size_t)b*2048 + idx];
    }

    const float* src0 = inputs + ((size_t)b*NN + g*(NTILE*TN))*IND;
#define PREFETCH(j, buf) do {                                                   \
        const float* _s = src0 + (size_t)(j)*TN*IND;                            \
        float* _d = Xs + (buf)*8192;                                            \
        _Pragma("unroll")                                                       \
        for (int p = 0; p < 4; ++p){                                            \
            int idx = t + p*512;                                                \
            int n = idx >> 6, k4 = idx & 63;                                    \
            uint32_t sa = (uint32_t)__cvta_generic_to_shared(                   \
                              &_d[(n*64 + (k4 ^ (n & 7)))*4]);                  \
            asm volatile("cp.async.cg.shared.global [%0], [%1], 16;"            \
                         :: "r"(sa), "l"(_s + (size_t)n*IND + k4*4) : "memory");\
        }                                                                       \
        asm volatile("cp.async.commit_group;" ::: "memory");                    \
    } while(0)

    PREFETCH(0, 0);

    float m_run = -3.4e38f, lpart = 0.f;
    float uacc[4] = {};
    const int sh = (t >= 256) ? 4 : 0;     // phase3 slot-half
    const int e  = t & 255;
    const int e4 = e >> 2, eo = e & 3;
    const int ks = t >> 5;                 // phase1 k-slice (= warp id)
    const int pn = t & 31;                 // phase1 n (= lane)

    // ---- hoisted swizzle address math ----
    const int c  = pn & 7;
    const int p1base = pn*256 + ((ks*4) ^ (c & 4))*4;
    int a1[4];
#pragma unroll
    for (int i = 0; i < 4; ++i) a1[i] = p1base + (i ^ (c & 3))*4;
    int off3[8];
#pragma unroll
    for (int cc = 0; cc < 8; ++cc) off3[cc] = (e4 ^ cc)*4 + eo;

    for (int j = 0; j < NTILE; ++j){
        int buf = j & 1;
        asm volatile("cp.async.wait_group 0;" ::: "memory");
        __syncthreads();                                   // S1: tile ready, prior reads done
        if (j + 1 < NTILE) PREFETCH(j + 1, buf ^ 1);
        const float* Xb = Xs + buf*8192;

        // ---- phase 1: logits partials; warp = k-slice (16 k), lane = n ----
        {
            float acc[8] = {};
#pragma unroll
            for (int i = 0; i < 4; ++i){
                float4 x4 = *(const float4*)&Xb[a1[i]];
                int k = (ks*4 + i)*4;
                float xv[4] = {x4.x, x4.y, x4.z, x4.w};
#pragma unroll
                for (int d = 0; d < 4; ++d){
                    float4 qa = *(const float4*)&qT[(k+d)*8];
                    float4 qb = *(const float4*)&qT[(k+d)*8 + 4];
                    acc[0] += xv[d]*qa.x; acc[1] += xv[d]*qa.y;
                    acc[2] += xv[d]*qa.z; acc[3] += xv[d]*qa.w;
                    acc[4] += xv[d]*qb.x; acc[5] += xv[d]*qb.y;
                    acc[6] += xv[d]*qb.z; acc[7] += xv[d]*qb.w;
                }
            }
#pragma unroll
            for (int s = 0; s < 8; ++s) lgp[ks*256 + s*32 + pn] = acc[s];
        }
        __syncthreads();                                   // S2: lgp ready

        // ---- phase 2: online softmax; warp w<8 owns slot w, lane = key ----
        if (w < 8){
            float lg = 0.f;
#pragma unroll
            for (int kq = 0; kq < 16; ++kq) lg += lgp[kq*256 + w*32 + l];
            float mv = warpMax(lg);
            float m_new = fmaxf(m_run, mv);
            float ev = __expf(lg - m_new);
            atT[l*12 + w] = ev;
            float sc = __expf(m_run - m_new);
            lpart = lpart*sc + ev;
            m_run = m_new;
            if (l == 0) scs[w] = sc;
        }
        __syncthreads();                                   // S3: atT/scs ready

        // ---- phase 3: U accumulation; halves own slots sh..sh+3, col e ----
        {
            float4 sv = *(const float4*)&scs[sh];
            uacc[0] *= sv.x; uacc[1] *= sv.y; uacc[2] *= sv.z; uacc[3] *= sv.w;
            for (int n8 = 0; n8 < TN; n8 += 8){
#pragma unroll
                for (int cc = 0; cc < 8; ++cc){
                    int n = n8 + cc;
                    float x = Xb[n*256 + off3[cc]];
                    float4 a = *(const float4*)&atT[n*12 + sh];
                    uacc[0] += a.x*x; uacc[1] += a.y*x;
                    uacc[2] += a.z*x; uacc[3] += a.w*x;
                }
            }
        }
    }
#undef PREFETCH

#pragma unroll
    for (int i = 0; i < 4; ++i)
        upart[((size_t)g*ROWS + b*SS + sh + i)*IND + e] = uacc[i];
    if (w < 8){
        float l_run = warpSum(lpart);
        if (l == 0){
            int row = b*SS + w;
            mbuf[(size_t)g*ROWS + row] = m_run;
            lbuf[(size_t)g*ROWS + row] = l_run;
        }
    }
}

// ============ POST, 512 threads: fused gi (wf on U) + gh concurrent, then MLP ========
__global__ __launch_bounds__(512) void post_kernel(
        const float* __restrict__ upart,
        const float* __restrict__ mbuf, const float* __restrict__ lbuf,
        const float* __restrict__ wf,   const float* __restrict__ bf,
        const float* __restrict__ W_hh, const float* __restrict__ b_hh,
        const float* __restrict__ lng,  const float* __restrict__ lnb,
        const float* __restrict__ W1,   const float* __restrict__ b1,
        const float* __restrict__ W2,   const float* __restrict__ b2,
        const float* __restrict__ slots_in,
        float* __restrict__ dst)
{
    extern __shared__ float dsm[];
    float (*sBufA)[DD] = (float(*)[DD])(dsm);           // 1024  U / sln
    float (*sprev)[DD] = (float(*)[DD])(dsm + 1024);    // 1024
    float (*sBufB)[DD] = (float(*)[DD])(dsm + 2048);    // 1024  hidden
    float* sGh         = dsm + 3072;                    // 3072  gh[3][4][256]
    float (*sPar)[DD]  = (float(*)[DD])(dsm + 6144);    // 1024  split-k partials
    float* sWtA        = dsm + 7168;                    // 9216
    float* sWtB        = dsm + 16384;                   // 9216

    __shared__ float ssc[4][17];
    __shared__ float sinv[4];

    int r0 = blockIdx.x * 4;
    int t  = threadIdx.x;
    int tc = t & 255, grp = t >> 8;
    int w  = t >> 5, l = t & 31;
    float* myWt = grp ? sWtB : sWtA;

    // 1. per-row combine scales over NG=16 groups (warps 0-3, lanes 0-15)
    if (w < 4){
        int row = r0 + w;
        float mv = (l < NG) ? __ldg(&mbuf[(size_t)l*ROWS + row]) : -3.4e38f;
        float mm = mv;
        mm = fmaxf(mm, __shfl_xor_sync(0xffffffffu, mm, 1));
        mm = fmaxf(mm, __shfl_xor_sync(0xffffffffu, mm, 2));
        mm = fmaxf(mm, __shfl_xor_sync(0xffffffffu, mm, 4));
        mm = fmaxf(mm, __shfl_xor_sync(0xffffffffu, mm, 8));
        float e  = (l < NG) ? __expf(mv - mm) : 0.f;
        float lv = (l < NG) ? __ldg(&lbuf[(size_t)l*ROWS + row]) * e : 0.f;
        lv += __shfl_xor_sync(0xffffffffu, lv, 1);
        lv += __shfl_xor_sync(0xffffffffu, lv, 2);
        lv += __shfl_xor_sync(0xffffffffu, lv, 4);
        lv += __shfl_xor_sync(0xffffffffu, lv, 8);
        if (l < NG) ssc[w][l] = e;
        if (l == 0) sinv[w] = 1.f / lv;
    }
    __syncthreads();

    // 2. U = (sum_g Ubar_g*sc_g)*inv ; load slots_prev (each thread 2 rows)
#pragma unroll
    for (int rr = 0; rr < 2; ++rr){
        int r = grp*2 + rr, row = r0 + r;
        float a = 0.f;
#pragma unroll
        for (int ch = 0; ch < NG; ++ch)
            a += __ldg(&upart[((size_t)ch*ROWS + row)*IND + tc]) * ssc[r][ch];
        sBufA[r][tc] = a * sinv[r];
        sprev[r][tc] = slots_in[(size_t)row*DD + tc];
    }
    // (first barrier inside gemm_tiles orders these writes)

    // 3. GRU gates concurrently: grp0 -> gi = U @ wf^T + bf ; grp1 -> gh on prev
    float acc[4];
    float gi[3][4];
#pragma unroll
    for (int j = 0; j < 3; ++j){
        const float* Wg = grp ? (W_hh + (size_t)j*DD*DD) : (wf + (size_t)j*DD*DD);
        const float (*Ag)[DD] = grp ? sprev : sBufA;
        gemm_tiles(Ag, Wg, myWt, acc, tc, 0, 8);
        if (grp == 0){
            float bb = __ldg(&bf[tc + j*256]);
#pragma unroll
            for (int r = 0; r < 4; ++r) gi[j][r] = acc[r] + bb;
        } else {
            float bb = __ldg(&b_hh[tc + j*256]);
#pragma unroll
            for (int r = 0; r < 4; ++r) sGh[(j*4 + r)*256 + tc] = acc[r] + bb;
        }
    }
    __syncthreads();

    // 4. GRU cell + residual (grp0)
    float vnew[4] = {0.f, 0.f, 0.f, 0.f};
    if (grp == 0){
#pragma unroll
        for (int r = 0; r < 4; ++r){
            float hr = sGh[(0*4 + r)*256 + tc];
            float hz = sGh[(1*4 + r)*256 + tc];
            float hn = sGh[(2*4 + r)*256 + tc];
            float rr = 1.f / (1.f + expf(-(gi[0][r] + hr)));
            float zz = 1.f / (1.f + expf(-(gi[1][r] + hz)));
            float nn = tanhf(gi[2][r] + rr*hn);
            float h  = sprev[r][tc];
            vnew[r]  = h + (1.f - zz)*nn + zz*h;
        }
    }

    // 5. LN(vnew) -> sBufA (grp0 data; all threads pass barriers)
    float lnv[4];
    block_ln4(vnew, lnv, lng, lnb, t);
    if (grp == 0){
#pragma unroll
        for (int r = 0; r < 4; ++r) sBufA[r][tc] = lnv[r];
    }

    // 6. hidden = relu(sln @ W1^T + b1) -> sBufB (split-K)
    gemm_tiles(sBufA, W1, myWt, acc, tc, grp*4, 4);
    if (grp == 1){
#pragma unroll
        for (int r = 0; r < 4; ++r) sPar[r][tc] = acc[r];
    }
    __syncthreads();
    if (grp == 0){
        float bb = __ldg(&b1[tc]);
#pragma unroll
        for (int r = 0; r < 4; ++r) sBufB[r][tc] = fmaxf(acc[r] + sPar[r][tc] + bb, 0.f);
    }

    // 7. out = vnew + hid @ W2^T + b2 (split-K)
    gemm_tiles(sBufB, W2, myWt, acc, tc, grp*4, 4);
    if (grp == 1){
#pragma unroll
        for (int r = 0; r < 4; ++r) sPar[r][tc] = acc[r];
    }
    __syncthreads();
    if (grp == 0){
        float bb = __ldg(&b2[tc]);
#pragma unroll
        for (int r = 0; r < 4; ++r)
            dst[(size_t)(r0+r)*DD + tc] = vnew[r] + acc[r] + sPar[r][tc] + bb;
    }
}

// ------------------------- host launcher -------------------------
extern "C" void kernel_launch(void* const* d_in, const int* in_sizes, int n_in,
                              void* d_out, int out_size)
{
    const float* inputs = (const float*)d_in[0];
    const float* noise  = (const float*)d_in[1];
    const float* s_mu   = (const float*)d_in[2];
    const float* s_sig  = (const float*)d_in[3];
    const float* Wq = (const float*)d_in[4];  const float* bq = (const float*)d_in[5];
    const float* Wk = (const float*)d_in[6];  /* bk = d_in[7] : dead (softmax shift-invariance) */
    const float* Wv = (const float*)d_in[8];  const float* bv = (const float*)d_in[9];
    const float* W_ih = (const float*)d_in[10]; const float* b_ih = (const float*)d_in[11];
    const float* W_hh = (const float*)d_in[12]; const float* b_hh = (const float*)d_in[13];
    const float* W1 = (const float*)d_in[14]; const float* b1 = (const float*)d_in[15];
    const float* W2 = (const float*)d_in[16]; const float* b2 = (const float*)d_in[17];
    const float* lnsg = (const float*)d_in[18]; const float* lnsb = (const float*)d_in[19];
    const float* lnmg = (const float*)d_in[20]; const float* lnmb = (const float*)d_in[21];
    float* out = (float*)d_out;
    (void)in_sizes; (void)n_in; (void)out_size;

    float *slots, *qW, *upart, *mbuf, *lbuf, *wqkT, *bqk, *wf, *bf;
    cudaGetSymbolAddress((void**)&slots, g_slots);
    cudaGetSymbolAddress((void**)&qW,    g_qW);
    cudaGetSymbolAddress((void**)&upart, g_upart);
    cudaGetSymbolAddress((void**)&mbuf,  g_m);
    cudaGetSymbolAddress((void**)&lbuf,  g_l);
    cudaGetSymbolAddress((void**)&wqkT,  g_wqkT);
    cudaGetSymbolAddress((void**)&bqk,   g_bqk);
    cudaGetSymbolAddress((void**)&wf,    g_wf);
    cudaGetSymbolAddress((void**)&bf,    g_bf);

    const int ATTN_SMEM = (16384 + 2048 + 4096 + 384 + 8) * 4;   // 91,680 B -> 2 blocks/SM
    const int POST_SMEM = (7168 + 9216*2) * 4;                   // 102,400 B
    const int PRE_SMEM  = (2048 + 9216*2) * 4;                   //  81,920 B
    static int s_init = 0;
    if (!s_init){
        cudaFuncSetAttribute(attn_kernel, cudaFuncAttributeMaxDynamicSharedMemorySize, ATTN_SMEM);
        cudaFuncSetAttribute(post_kernel, cudaFuncAttributeMaxDynamicSharedMemorySize, POST_SMEM);
        cudaFuncSetAttribute(pre_kernel,  cudaFuncAttributeMaxDynamicSharedMemorySize, PRE_SMEM);
        s_init = 1;
    }

    dim3 gBN(BB, NG);

    init_slots_kernel<<<ROWS, 256>>>(noise, s_mu, s_sig, slots);
    fuse_gemm_kernel<<<64, 256>>>(Wq, Wk, W_ih, Wv, wqkT, wf);
    fuse_bias_kernel<<<4, 256>>>(bq, Wk, W_ih, bv, b_ih, bqk, bf);

    for (int it = 0; it < 3; ++it){
        pre_kernel<<<ROWS/4, 512, PRE_SMEM>>>(slots, lnsg, lnsb, wqkT, bqk, qW);
        attn_kernel<<<gBN, 512, ATTN_SMEM>>>(qW, inputs, upart, mbuf, lbuf);
        float* dst = (it == 2) ? out : slots;
        post_kernel<<<ROWS/4, 512, POST_SMEM>>>(upart, mbuf, lbuf, wf, bf, W_hh, b_hh,
                                                lnmg, lnmb, W1, b1, W2, b2, slots, dst);
    }
}

// round 15
// speedup vs baseline: 1.0596x; 1.0110x over previous
#include <cuda_runtime.h>
#include <math.h>
#include <stdint.h>

// Problem constants
#define BB   64
#define NN   4096
#define IND  256
#define SS   8
#define DD   256
#define ROWS (BB*SS)        // 512
#define NG   16             // attention groups (blocks.y)
#define TN   32             // n's per tile
#define NTILE 8             // tiles per block (NG*NTILE*TN = 4096)

// -------- scratch (device globals; no allocation allowed) --------
__device__ float g_slots [ROWS*DD];
__device__ float g_qW    [ROWS*IND];
__device__ float g_upart [NG*ROWS*IND];   // unnormalized U partials (8 MB)
__device__ float g_m     [NG*ROWS];
__device__ float g_l     [NG*ROWS];
__device__ float g_wqkT  [IND*DD];        // ((Wq^T @ Wk)/16)^T : [e][d]
__device__ float g_bqk   [IND];           // (bq @ Wk)/16
__device__ float g_wf    [3*DD*DD];       // W_ih @ Wv
__device__ float g_bf    [3*DD];          // W_ih @ bv + b_ih

// -------- packed f32x2 helpers (sm_103a) --------
__device__ __forceinline__ unsigned long long f2pack(float x){
    unsigned long long r;
    asm("mov.b64 %0, {%1, %1};" : "=l"(r) : "f"(x));
    return r;
}
__device__ __forceinline__ unsigned long long fma2(unsigned long long a,
                                                   unsigned long long b,
                                                   unsigned long long c){
    unsigned long long d;
    asm("fma.rn.f32x2 %0, %1, %2, %3;" : "=l"(d) : "l"(a), "l"(b), "l"(c));
    return d;
}
__device__ __forceinline__ unsigned long long mul2(unsigned long long a,
                                                   unsigned long long b){
    unsigned long long d;
    asm("mul.rn.f32x2 %0, %1, %2;" : "=l"(d) : "l"(a), "l"(b));
    return d;
}
__device__ __forceinline__ void unpack2(unsigned long long v, float& lo, float& hi){
    asm("mov.b64 {%0, %1}, %2;" : "=f"(lo), "=f"(hi) : "l"(v));
}

// -------- reductions --------
__device__ __forceinline__ float warpSum(float v){
#pragma unroll
    for (int o = 16; o > 0; o >>= 1) v += __shfl_xor_sync(0xffffffffu, v, o);
    return v;
}
__device__ __forceinline__ float warpMax(float v){
#pragma unroll
    for (int o = 16; o > 0; o >>= 1) v = fmaxf(v, __shfl_xor_sync(0xffffffffu, v, o));
    return v;
}

// -------- slots = mu + sigma * noise --------
__global__ void init_slots_kernel(const float* __restrict__ noise,
                                  const float* __restrict__ mu,
                                  const float* __restrict__ sigma,
                                  float* __restrict__ slots){
    int i  = blockIdx.x * 256 + threadIdx.x;
    int sd = i & (SS*DD - 1);
    slots[i] = mu[sd] + sigma[sd] * noise[i];
}

// ============ one-off weight fusions ============
__global__ __launch_bounds__(256) void fuse_gemm_kernel(
        const float* __restrict__ Wq,   const float* __restrict__ Wk,
        const float* __restrict__ W_ih, const float* __restrict__ Wv,
        float* __restrict__ wqkT, float* __restrict__ wf)
{
    __shared__ float As[32][65];
    __shared__ float Bs[32][65];
    int b = blockIdx.x, t = threadIdx.x;
    int tx = t & 15, ty = t >> 4;
    int mode = (b >= 16);
    const float *A, *Bm; int m0, n0;
    if (!mode){ A = Wq;   Bm = Wk; m0 = (b>>2)*64;         n0 = (b&3)*64; }
    else      { int bb=b-16; A = W_ih; Bm = Wv; m0 = (bb>>2)*64; n0 = (bb&3)*64; }

    float acc[4][4] = {};
    for (int k0 = 0; k0 < 256; k0 += 32){
        if (!mode){
#pragma unroll
            for (int p = 0; p < 8; ++p){
                int idx = t + p*256;
                int kk = idx >> 6, mm = idx & 63;
                As[kk][mm] = A[(size_t)(k0+kk)*256 + m0 + mm];
            }
        } else {
#pragma unroll
            for (int p = 0; p < 8; ++p){
                int idx = t + p*256;
                int oo = idx >> 5, dd = idx & 31;
                As[dd][oo] = A[(size_t)(m0+oo)*256 + k0 + dd];
            }
        }
#pragma unroll
        for (int p = 0; p < 8; ++p){
            int idx = t + p*256;
            int kk = idx >> 6, nn = idx & 63;
            Bs[kk][nn] = Bm[(size_t)(k0+kk)*256 + n0 + nn];
        }
        __syncthreads();
#pragma unroll
        for (int kk = 0; kk < 32; ++kk){
            float av[4], bw[4];
#pragma unroll
            for (int i = 0; i < 4; ++i){ av[i] = As[kk][ty*4+i]; bw[i] = Bs[kk][tx*4+i]; }
#pragma unroll
            for (int i = 0; i < 4; ++i)
#pragma unroll
                for (int j = 0; j < 4; ++j) acc[i][j] += av[i]*bw[j];
        }
        __syncthreads();
    }
    if (!mode){
#pragma unroll
        for (int i = 0; i < 4; ++i)
#pragma unroll
            for (int j = 0; j < 4; ++j)
                wqkT[(size_t)(n0 + tx*4 + j)*256 + m0 + ty*4 + i] = acc[i][j]*0.0625f;
    } else {
#pragma unroll
        for (int i = 0; i < 4; ++i)
#pragma unroll
            for (int j = 0; j < 4; ++j)
                wf[(size_t)(m0 + ty*4 + i)*256 + n0 + tx*4 + j] = acc[i][j];
    }
}

__global__ __launch_bounds__(256) void fuse_bias_kernel(
        const float* __restrict__ bq,   const float* __restrict__ Wk,
        const float* __restrict__ W_ih, const float* __restrict__ bv,
        const float* __restrict__ b_ih,
        float* __restrict__ bqk, float* __restrict__ bf)
{
    int b = blockIdx.x, t = threadIdx.x;
    if (b == 0){
        float a = 0.f;
#pragma unroll 8
        for (int c = 0; c < 256; ++c) a += bq[c]*__ldg(&Wk[(size_t)c*256 + t]);
        bqk[t] = a * 0.0625f;
    } else {
        int o = (b-1)*256 + t;
        const float4* row = reinterpret_cast<const float4*>(W_ih + (size_t)o*256);
        const float4* vv  = reinterpret_cast<const float4*>(bv);
        float a = 0.f;
#pragma unroll 8
        for (int k4 = 0; k4 < 64; ++k4){
            float4 wv = __ldg(&row[k4]);
            float4 bw = __ldg(&vv[k4]);
            a += wv.x*bw.x + wv.y*bw.y + wv.z*bw.z + wv.w*bw.w;
        }
        bf[o] = a + b_ih[o];
    }
}

// Block LayerNorm (256-thread data path; callable from 256 OR 512 threads).
__device__ __forceinline__ void block_ln4(const float v[4], float o[4],
                                          const float* __restrict__ g,
                                          const float* __restrict__ b, int t)
{
    __shared__ float part[8][4];
    __shared__ float stat[4];
    int w = t >> 5, l = t & 31;
#pragma unroll
    for (int r = 0; r < 4; ++r){
        float p = warpSum(v[r]);
        if (l == 0 && w < 8) part[w][r] = p;
    }
    __syncthreads();
    if (t < 32){
        int rr = l >> 3, ww = l & 7;
        float x = part[ww][rr];
        x += __shfl_xor_sync(0xffffffffu, x, 1);
        x += __shfl_xor_sync(0xffffffffu, x, 2);
        x += __shfl_xor_sync(0xffffffffu, x, 4);
        if (ww == 0) stat[rr] = x * (1.f/256.f);
    }
    __syncthreads();
    float d[4];
#pragma unroll
    for (int r = 0; r < 4; ++r) d[r] = v[r] - stat[r];
    __syncthreads();
#pragma unroll
    for (int r = 0; r < 4; ++r){
        float p = warpSum(d[r]*d[r]);
        if (l == 0 && w < 8) part[w][r] = p;
    }
    __syncthreads();
    if (t < 32){
        int rr = l >> 3, ww = l & 7;
        float x = part[ww][rr];
        x += __shfl_xor_sync(0xffffffffu, x, 1);
        x += __shfl_xor_sync(0xffffffffu, x, 2);
        x += __shfl_xor_sync(0xffffffffu, x, 4);
        if (ww == 0) stat[rr] = rsqrtf(x * (1.f/256.f) + 1e-5f);
    }
    __syncthreads();
    int tc = t & 255;
    float gg = g[tc], bb = b[tc];
#pragma unroll
    for (int r = 0; r < 4; ++r) o[r] = d[r] * stat[r] * gg + bb;
}

// ============ gemm_tiles v2: row-major staging (STS.128 in, LDS.128 out) ============
__device__ __forceinline__ void gemm_tiles(
        const float (*sA)[DD],
        const float* __restrict__ W,
        float* __restrict__ sWt,     // this group's staging [256][36]
        float acc[4], int tc, int ktStart, int ktCount)
{
    const float4* Wp = reinterpret_cast<const float4*>(W);
    float4 r[8];
#pragma unroll
    for (int p = 0; p < 8; ++p){
        int idx = tc + p*256;
        r[p] = __ldg(&Wp[(size_t)(idx >> 3)*64 + ktStart*8 + (idx & 7)]);
    }
    acc[0] = acc[1] = acc[2] = acc[3] = 0.f;

    for (int kt = 0; kt < ktCount; ++kt){
        __syncthreads();
#pragma unroll
        for (int p = 0; p < 8; ++p){
            int idx = tc + p*256;
            *reinterpret_cast<float4*>(&sWt[(idx >> 3)*36 + (idx & 7)*4]) = r[p];
        }
        __syncthreads();
        if (kt + 1 < ktCount){
#pragma unroll
            for (int p = 0; p < 8; ++p){
                int idx = tc + p*256;
                r[p] = __ldg(&Wp[(size_t)(idx >> 3)*64 + (ktStart+kt+1)*8 + (idx & 7)]);
            }
        }
        int kb = (ktStart + kt)*32;
#pragma unroll
        for (int kk4 = 0; kk4 < 8; ++kk4){
            float4 a0 = *(const float4*)&sA[0][kb + kk4*4];
            float4 a1 = *(const float4*)&sA[1][kb + kk4*4];
            float4 a2 = *(const float4*)&sA[2][kb + kk4*4];
            float4 a3 = *(const float4*)&sA[3][kb + kk4*4];
            float4 wv = *(const float4*)&sWt[tc*36 + kk4*4];
            acc[0] += a0.x*wv.x + a0.y*wv.y + a0.z*wv.z + a0.w*wv.w;
            acc[1] += a1.x*wv.x + a1.y*wv.y + a1.z*wv.z + a1.w*wv.w;
            acc[2] += a2.x*wv.x + a2.y*wv.y + a2.z*wv.z + a2.w*wv.w;
            acc[3] += a3.x*wv.x + a3.y*wv.y + a3.z*wv.z + a3.w*wv.w;
        }
    }
}

// ============ PRE, 512 threads: LN -> qW = LN @ wqkT^T + bqk via gemm_tiles ==========
__global__ __launch_bounds__(512) void pre_kernel(
        const float* __restrict__ slots,
        const float* __restrict__ lng, const float* __restrict__ lnb,
        const float* __restrict__ wqkT, const float* __restrict__ bqk,
        float* __restrict__ qW)
{
    extern __shared__ float dsm[];
    float (*s_ln)[DD] = (float(*)[DD])(dsm);            // 1024
    float (*sPar)[DD] = (float(*)[DD])(dsm + 1024);     // 1024
    float* sWtA       = dsm + 2048;                     // 9216
    float* sWtB       = dsm + 11264;                    // 9216

    int r0 = blockIdx.x * 4;
    int t  = threadIdx.x;
    int tc = t & 255, grp = t >> 8;
    float* myWt = grp ? sWtB : sWtA;

    float v[4] = {0.f, 0.f, 0.f, 0.f};
    if (grp == 0){
#pragma unroll
        for (int r = 0; r < 4; ++r) v[r] = slots[(size_t)(r0+r)*DD + tc];
    }
    float o[4];
    block_ln4(v, o, lng, lnb, t);
    if (grp == 0){
#pragma unroll
        for (int r = 0; r < 4; ++r) s_ln[r][tc] = o[r];
    }

    float acc[4];
    gemm_tiles(s_ln, wqkT, myWt, acc, tc, grp*4, 4);
    if (grp == 1){
#pragma unroll
        for (int r = 0; r < 4; ++r) sPar[r][tc] = acc[r];
    }
    __syncthreads();
    if (grp == 0){
        float bb = __ldg(&bqk[tc]);
        qW[(size_t)(r0+0)*IND + tc] = acc[0] + sPar[0][tc] + bb;
        qW[(size_t)(r0+1)*IND + tc] = acc[1] + sPar[1][tc] + bb;
        qW[(size_t)(r0+2)*IND + tc] = acc[2] + sPar[2][tc] + bb;
        qW[(size_t)(r0+3)*IND + tc] = acc[3] + sPar[3][tc] + bb;
    }
}

// ============ FLASH attention, TN=32, f32x2 dual-FMA in phases 1 & 3 ============
__global__ __launch_bounds__(512, 2) void attn_kernel(
        const float* __restrict__ qW,
        const float* __restrict__ inputs,
        float* __restrict__ upart,
        float* __restrict__ mbuf,
        float* __restrict__ lbuf)
{
    extern __shared__ float dsm[];
    float* Xs  = dsm;                  // 2 * 8192 floats (64 KB)
    float* qT  = dsm + 16384;          // [k][s] 2048
    float* lgp = qT  + 2048;           // [ks][s][n] 16*8*32 = 4096
    float* atT = lgp + 4096;           // [n][12] 384
    float* scs = atT + 384;            // 8

    int b = blockIdx.x, g = blockIdx.y;
    int t = threadIdx.x, w = t >> 5, l = t & 31;

    // stage qT
#pragma unroll
    for (int p = 0; p < 4; ++p){
        int idx = t + p*512;
        qT[(idx & 255)*8 + (idx >> 8)] = qW[(size_t)b*2048 + idx];
    }

    const float* src0 = inputs + ((size_t)b*NN + g*(NTILE*TN))*IND;
#define PREFETCH(j, buf) do {                                                   \
        const float* _s = src0 + (size_t)(j)*TN*IND;                            \
        float* _d = Xs + (buf)*8192;                                            \
        _Pragma("unroll")                                                       \
        for (int p = 0; p < 4; ++p){                                            \
            int idx = t + p*512;                                                \
            int n = idx >> 6, k4 = idx & 63;                                    \
            uint32_t sa = (uint32_t)__cvta_generic_to_shared(                   \
                              &_d[(n*64 + (k4 ^ (n & 7)))*4]);                  \
            asm volatile("cp.async.cg.shared.global [%0], [%1], 16;"            \
                         :: "r"(sa), "l"(_s + (size_t)n*IND + k4*4) : "memory");\
        }                                                                       \
        asm volatile("cp.async.commit_group;" ::: "memory");                    \
    } while(0)

    PREFETCH(0, 0);

    float m_run = -3.4e38f, lpart = 0.f;
    unsigned long long u01 = 0ull, u23 = 0ull;   // packed U accumulators (slot pairs)
    const int sh = (t >= 256) ? 4 : 0;     // phase3 slot-half
    const int e  = t & 255;
    const int e4 = e >> 2, eo = e & 3;
    const int ks = t >> 5;                 // phase1 k-slice (= warp id)
    const int pn = t & 31;                 // phase1 n (= lane)

    // ---- hoisted swizzle address math ----
    const int c  = pn & 7;
    const int p1base = pn*256 + ((ks*4) ^ (c & 4))*4;
    int a1[4];
#pragma unroll
    for (int i = 0; i < 4; ++i) a1[i] = p1base + (i ^ (c & 3))*4;
    int off3[8];
#pragma unroll
    for (int cc = 0; cc < 8; ++cc) off3[cc] = (e4 ^ cc)*4 + eo;

    for (int j = 0; j < NTILE; ++j){
        int buf = j & 1;
        asm volatile("cp.async.wait_group 0;" ::: "memory");
        __syncthreads();                                   // S1: tile ready, prior reads done
        if (j + 1 < NTILE) PREFETCH(j + 1, buf ^ 1);
        const float* Xb = Xs + buf*8192;

        // ---- phase 1: logits partials (packed f32x2; slot pairs) ----
        {
            unsigned long long a01 = 0ull, a23 = 0ull, a45 = 0ull, a67 = 0ull;
#pragma unroll
            for (int i = 0; i < 4; ++i){
                float4 x4 = *(const float4*)&Xb[a1[i]];
                int k = (ks*4 + i)*4;
                float xv[4] = {x4.x, x4.y, x4.z, x4.w};
#pragma unroll
                for (int d = 0; d < 4; ++d){
                    unsigned long long xx = f2pack(xv[d]);
                    ulonglong2 qlo = *(const ulonglong2*)&qT[(k+d)*8];
                    ulonglong2 qhi = *(const ulonglong2*)&qT[(k+d)*8 + 4];
                    a01 = fma2(xx, qlo.x, a01);
                    a23 = fma2(xx, qlo.y, a23);
                    a45 = fma2(xx, qhi.x, a45);
                    a67 = fma2(xx, qhi.y, a67);
                }
            }
            float s0,s1,s2,s3,s4,s5,s6,s7;
            unpack2(a01, s0, s1); unpack2(a23, s2, s3);
            unpack2(a45, s4, s5); unpack2(a67, s6, s7);
            lgp[ks*256 + 0*32 + pn] = s0; lgp[ks*256 + 1*32 + pn] = s1;
            lgp[ks*256 + 2*32 + pn] = s2; lgp[ks*256 + 3*32 + pn] = s3;
            lgp[ks*256 + 4*32 + pn] = s4; lgp[ks*256 + 5*32 + pn] = s5;
            lgp[ks*256 + 6*32 + pn] = s6; lgp[ks*256 + 7*32 + pn] = s7;
        }
        __syncthreads();                                   // S2: lgp ready

        // ---- phase 2: online softmax; warp w<8 owns slot w, lane = key ----
        if (w < 8){
            float lg = 0.f;
#pragma unroll
            for (int kq = 0; kq < 16; ++kq) lg += lgp[kq*256 + w*32 + l];
            float mv = warpMax(lg);
            float m_new = fmaxf(m_run, mv);
            float ev = __expf(lg - m_new);
            atT[l*12 + w] = ev;
            float sc = __expf(m_run - m_new);
            lpart = lpart*sc + ev;
            m_run = m_new;
            if (l == 0) scs[w] = sc;
        }
        __syncthreads();                                   // S3: atT/scs ready

        // ---- phase 3: U accumulation (packed f32x2; slot pairs) ----
        {
            ulonglong2 sv2 = *(const ulonglong2*)&scs[sh];
            u01 = mul2(u01, sv2.x);
            u23 = mul2(u23, sv2.y);
            for (int n8 = 0; n8 < TN; n8 += 8){
#pragma unroll
                for (int cc = 0; cc < 8; ++cc){
                    int n = n8 + cc;
                    unsigned long long xx = f2pack(Xb[n*256 + off3[cc]]);
                    ulonglong2 a2 = *(const ulonglong2*)&atT[n*12 + sh];
                    u01 = fma2(xx, a2.x, u01);
                    u23 = fma2(xx, a2.y, u23);
                }
            }
        }
    }
#undef PREFETCH

    {
        float v0,v1,v2,v3;
        unpack2(u01, v0, v1); unpack2(u23, v2, v3);
        size_t base = ((size_t)g*ROWS + b*SS + sh)*IND + e;
        upart[base          ] = v0;
        upart[base +   IND  ] = v1;
        upart[base + 2*IND  ] = v2;
        upart[base + 3*IND  ] = v3;
    }
    if (w < 8){
        float l_run = warpSum(lpart);
        if (l == 0){
            int row = b*SS + w;
            mbuf[(size_t)g*ROWS + row] = m_run;
            lbuf[(size_t)g*ROWS + row] = l_run;
        }
    }
}

// ============ POST, 512 threads: fused gi (wf on U) + gh concurrent, then MLP ========
__global__ __launch_bounds__(512) void post_kernel(
        const float* __restrict__ upart,
        const float* __restrict__ mbuf, const float* __restrict__ lbuf,
        const float* __restrict__ wf,   const float* __restrict__ bf,
        const float* __restrict__ W_hh, const float* __restrict__ b_hh,
        const float* __restrict__ lng,  const float* __restrict__ lnb,
        const float* __restrict__ W1,   const float* __restrict__ b1,
        const float* __restrict__ W2,   const float* __restrict__ b2,
        const float* __restrict__ slots_in,
        float* __restrict__ dst)
{
    extern __shared__ float dsm[];
    float (*sBufA)[DD] = (float(*)[DD])(dsm);           // 1024  U / sln
    float (*sprev)[DD] = (float(*)[DD])(dsm + 1024);    // 1024
    float (*sBufB)[DD] = (float(*)[DD])(dsm + 2048);    // 1024  hidden
    float* sGh         = dsm + 3072;                    // 3072  gh[3][4][256]
    float (*sPar)[DD]  = (float(*)[DD])(dsm + 6144);    // 1024  split-k partials
    float* sWtA        = dsm + 7168;                    // 9216
    float* sWtB        = dsm + 16384;                   // 9216

    __shared__ float ssc[4][17];
    __shared__ float sinv[4];

    int r0 = blockIdx.x * 4;
    int t  = threadIdx.x;
    int tc = t & 255, grp = t >> 8;
    int w  = t >> 5, l = t & 31;
    float* myWt = grp ? sWtB : sWtA;

    // 1. per-row combine scales over NG=16 groups (warps 0-3, lanes 0-15)
    if (w < 4){
        int row = r0 + w;
        float mv = (l < NG) ? __ldg(&mbuf[(size_t)l*ROWS + row]) : -3.4e38f;
        float mm = mv;
        mm = fmaxf(mm, __shfl_xor_sync(0xffffffffu, mm, 1));
        mm = fmaxf(mm, __shfl_xor_sync(0xffffffffu, mm, 2));
        mm = fmaxf(mm, __shfl_xor_sync(0xffffffffu, mm, 4));
        mm = fmaxf(mm, __shfl_xor_sync(0xffffffffu, mm, 8));
        float e  = (l < NG) ? __expf(mv - mm) : 0.f;
        float lv = (l < NG) ? __ldg(&lbuf[(size_t)l*ROWS + row]) * e : 0.f;
        lv += __shfl_xor_sync(0xffffffffu, lv, 1);
        lv += __shfl_xor_sync(0xffffffffu, lv, 2);
        lv += __shfl_xor_sync(0xffffffffu, lv, 4);
        lv += __shfl_xor_sync(0xffffffffu, lv, 8);
        if (l < NG) ssc[w][l] = e;
        if (l == 0) sinv[w] = 1.f / lv;
    }
    __syncthreads();

    // 2. U = (sum_g Ubar_g*sc_g)*inv ; load slots_prev (each thread 2 rows)
#pragma unroll
    for (int rr = 0; rr < 2; ++rr){
        int r = grp*2 + rr, row = r0 + r;
        float a = 0.f;
#pragma unroll
        for (int ch = 0; ch < NG; ++ch)
            a += __ldg(&upart[((size_t)ch*ROWS + row)*IND + tc]) * ssc[r][ch];
        sBufA[r][tc] = a * sinv[r];
        sprev[r][tc] = slots_in[(size_t)row*DD + tc];
    }
    // (first barrier inside gemm_tiles orders these writes)

    // 3. GRU gates concurrently: grp0 -> gi = U @ wf^T + bf ; grp1 -> gh on prev
    float acc[4];
    float gi[3][4];
#pragma unroll
    for (int j = 0; j < 3; ++j){
        const float* Wg = grp ? (W_hh + (size_t)j*DD*DD) : (wf + (size_t)j*DD*DD);
        const float (*Ag)[DD] = grp ? sprev : sBufA;
        gemm_tiles(Ag, Wg, myWt, acc, tc, 0, 8);
        if (grp == 0){
            float bb = __ldg(&bf[tc + j*256]);
#pragma unroll
            for (int r = 0; r < 4; ++r) gi[j][r] = acc[r] + bb;
        } else {
            float bb = __ldg(&b_hh[tc + j*256]);
#pragma unroll
            for (int r = 0; r < 4; ++r) sGh[(j*4 + r)*256 + tc] = acc[r] + bb;
        }
    }
    __syncthreads();

    // 4. GRU cell + residual (grp0)
    float vnew[4] = {0.f, 0.f, 0.f, 0.f};
    if (grp == 0){
#pragma unroll
        for (int r = 0; r < 4; ++r){
            float hr = sGh[(0*4 + r)*256 + tc];
            float hz = sGh[(1*4 + r)*256 + tc];
            float hn = sGh[(2*4 + r)*256 + tc];
            float rr = 1.f / (1.f + expf(-(gi[0][r] + hr)));
            float zz = 1.f / (1.f + expf(-(gi[1][r] + hz)));
            float nn = tanhf(gi[2][r] + rr*hn);
            float h  = sprev[r][tc];
            vnew[r]  = h + (1.f - zz)*nn + zz*h;
        }
    }

    // 5. LN(vnew) -> sBufA (grp0 data; all threads pass barriers)
    float lnv[4];
    block_ln4(vnew, lnv, lng, lnb, t);
    if (grp == 0){
#pragma unroll
        for (int r = 0; r < 4; ++r) sBufA[r][tc] = lnv[r];
    }

    // 6. hidden = relu(sln @ W1^T + b1) -> sBufB (split-K)
    gemm_tiles(sBufA, W1, myWt, acc, tc, grp*4, 4);
    if (grp == 1){
#pragma unroll
        for (int r = 0; r < 4; ++r) sPar[r][tc] = acc[r];
    }
    __syncthreads();
    if (grp == 0){
        float bb = __ldg(&b1[tc]);
#pragma unroll
        for (int r = 0; r < 4; ++r) sBufB[r][tc] = fmaxf(acc[r] + sPar[r][tc] + bb, 0.f);
    }

    // 7. out = vnew + hid @ W2^T + b2 (split-K)
    gemm_tiles(sBufB, W2, myWt, acc, tc, grp*4, 4);
    if (grp == 1){
#pragma unroll
        for (int r = 0; r < 4; ++r) sPar[r][tc] = acc[r];
    }
    __syncthreads();
    if (grp == 0){
        float bb = __ldg(&b2[tc]);
#pragma unroll
        for (int r = 0; r < 4; ++r)
            dst[(size_t)(r0+r)*DD + tc] = vnew[r] + acc[r] + sPar[r][tc] + bb;
    }
}

// ------------------------- host launcher -------------------------
extern "C" void kernel_launch(void* const* d_in, const int* in_sizes, int n_in,
                              void* d_out, int out_size)
{
    const float* inputs = (const float*)d_in[0];
    const float* noise  = (const float*)d_in[1];
    const float* s_mu   = (const float*)d_in[2];
    const float* s_sig  = (const float*)d_in[3];
    const float* Wq = (const float*)d_in[4];  const float* bq = (const float*)d_in[5];
    const float* Wk = (const float*)d_in[6];  /* bk = d_in[7] : dead (softmax shift-invariance) */
    const float* Wv = (const float*)d_in[8];  const float* bv = (const float*)d_in[9];
    const float* W_ih = (const float*)d_in[10]; const float* b_ih = (const float*)d_in[11];
    const float* W_hh = (const float*)d_in[12]; const float* b_hh = (const float*)d_in[13];
    const float* W1 = (const float*)d_in[14]; const float* b1 = (const float*)d_in[15];
    const float* W2 = (const float*)d_in[16]; const float* b2 = (const float*)d_in[17];
    const float* lnsg = (const float*)d_in[18]; const float* lnsb = (const float*)d_in[19];
    const float* lnmg = (const float*)d_in[20]; const float* lnmb = (const float*)d_in[21];
    float* out = (float*)d_out;
    (void)in_sizes; (void)n_in; (void)out_size;

    float *slots, *qW, *upart, *mbuf, *lbuf, *wqkT, *bqk, *wf, *bf;
    cudaGetSymbolAddress((void**)&slots, g_slots);
    cudaGetSymbolAddress((void**)&qW,    g_qW);
    cudaGetSymbolAddress((void**)&upart, g_upart);
    cudaGetSymbolAddress((void**)&mbuf,  g_m);
    cudaGetSymbolAddress((void**)&lbuf,  g_l);
    cudaGetSymbolAddress((void**)&wqkT,  g_wqkT);
    cudaGetSymbolAddress((void**)&bqk,   g_bqk);
    cudaGetSymbolAddress((void**)&wf,    g_wf);
    cudaGetSymbolAddress((void**)&bf,    g_bf);

    const int ATTN_SMEM = (16384 + 2048 + 4096 + 384 + 8) * 4;   // 91,680 B -> 2 blocks/SM
    const int POST_SMEM = (7168 + 9216*2) * 4;                   // 102,400 B
    const int PRE_SMEM  = (2048 + 9216*2) * 4;                   //  81,920 B
    static int s_init = 0;
    if (!s_init){
        cudaFuncSetAttribute(attn_kernel, cudaFuncAttributeMaxDynamicSharedMemorySize, ATTN_SMEM);
        cudaFuncSetAttribute(post_kernel, cudaFuncAttributeMaxDynamicSharedMemorySize, POST_SMEM);
        cudaFuncSetAttribute(pre_kernel,  cudaFuncAttributeMaxDynamicSharedMemorySize, PRE_SMEM);
        s_init = 1;
    }

    dim3 gBN(BB, NG);

    init_slots_kernel<<<ROWS, 256>>>(noise, s_mu, s_sig, slots);
    fuse_gemm_kernel<<<64, 256>>>(Wq, Wk, W_ih, Wv, wqkT, wf);
    fuse_bias_kernel<<<4, 256>>>(bq, Wk, W_ih, bv, b_ih, bqk, bf);

    for (int it = 0; it < 3; ++it){
        pre_kernel<<<ROWS/4, 512, PRE_SMEM>>>(slots, lnsg, lnsb, wqkT, bqk, qW);
        attn_kernel<<<gBN, 512, ATTN_SMEM>>>(qW, inputs, upart, mbuf, lbuf);
        float* dst = (it == 2) ? out : slots;
        post_kernel<<<ROWS/4, 512, POST_SMEM>>>(upart, mbuf, lbuf, wf, bf, W_hh, b_hh,
                                                lnmg, lnmb, W1, b1, W2, b2, slots, dst);
    }
}

// round 16
// speedup vs baseline: 1.0635x; 1.0038x over previous
#include <cuda_runtime.h>
#include <math.h>
#include <stdint.h>

// Problem constants
#define BB   64
#define NN   4096
#define IND  256
#define SS   8
#define DD   256
#define ROWS (BB*SS)        // 512
#define NG   16             // attention groups (blocks.y)
#define TN   32             // n's per tile
#define NTILE 8             // tiles per block (NG*NTILE*TN = 4096)

// -------- scratch (device globals; no allocation allowed) --------
__device__ float g_slots [ROWS*DD];
__device__ float g_qW    [ROWS*IND];
__device__ float g_upart [NG*ROWS*IND];   // unnormalized U partials (8 MB)
__device__ float g_m     [NG*ROWS];
__device__ float g_l     [NG*ROWS];
__device__ float g_wqkT  [IND*DD];        // ((Wq^T @ Wk)/16)^T : [e][d]
__device__ float g_bqk   [IND];           // (bq @ Wk)/16
__device__ float g_wf    [3*DD*DD];       // W_ih @ Wv
__device__ float g_bf    [3*DD];          // W_ih @ bv + b_ih

// -------- packed f32x2 helpers (sm_103a) --------
__device__ __forceinline__ unsigned long long f2pack(float x){
    unsigned long long r;
    asm("mov.b64 %0, {%1, %1};" : "=l"(r) : "f"(x));
    return r;
}
__device__ __forceinline__ unsigned long long fma2(unsigned long long a,
                                                   unsigned long long b,
                                                   unsigned long long c){
    unsigned long long d;
    asm("fma.rn.f32x2 %0, %1, %2, %3;" : "=l"(d) : "l"(a), "l"(b), "l"(c));
    return d;
}
__device__ __forceinline__ unsigned long long mul2(unsigned long long a,
                                                   unsigned long long b){
    unsigned long long d;
    asm("mul.rn.f32x2 %0, %1, %2;" : "=l"(d) : "l"(a), "l"(b));
    return d;
}
__device__ __forceinline__ void unpack2(unsigned long long v, float& lo, float& hi){
    asm("mov.b64 {%0, %1}, %2;" : "=f"(lo), "=f"(hi) : "l"(v));
}

// -------- reductions --------
__device__ __forceinline__ float warpSum(float v){
#pragma unroll
    for (int o = 16; o > 0; o >>= 1) v += __shfl_xor_sync(0xffffffffu, v, o);
    return v;
}
__device__ __forceinline__ float warpMax(float v){
#pragma unroll
    for (int o = 16; o > 0; o >>= 1) v = fmaxf(v, __shfl_xor_sync(0xffffffffu, v, o));
    return v;
}

// -------- slots = mu + sigma * noise --------
__global__ void init_slots_kernel(const float* __restrict__ noise,
                                  const float* __restrict__ mu,
                                  const float* __restrict__ sigma,
                                  float* __restrict__ slots){
    int i  = blockIdx.x * 256 + threadIdx.x;
    int sd = i & (SS*DD - 1);
    slots[i] = mu[sd] + sigma[sd] * noise[i];
}

// ============ one-off weight fusions ============
__global__ __launch_bounds__(256) void fuse_gemm_kernel(
        const float* __restrict__ Wq,   const float* __restrict__ Wk,
        const float* __restrict__ W_ih, const float* __restrict__ Wv,
        float* __restrict__ wqkT, float* __restrict__ wf)
{
    __shared__ float As[32][65];
    __shared__ float Bs[32][65];
    int b = blockIdx.x, t = threadIdx.x;
    int tx = t & 15, ty = t >> 4;
    int mode = (b >= 16);
    const float *A, *Bm; int m0, n0;
    if (!mode){ A = Wq;   Bm = Wk; m0 = (b>>2)*64;         n0 = (b&3)*64; }
    else      { int bb=b-16; A = W_ih; Bm = Wv; m0 = (bb>>2)*64; n0 = (bb&3)*64; }

    float acc[4][4] = {};
    for (int k0 = 0; k0 < 256; k0 += 32){
        if (!mode){
#pragma unroll
            for (int p = 0; p < 8; ++p){
                int idx = t + p*256;
                int kk = idx >> 6, mm = idx & 63;
                As[kk][mm] = A[(size_t)(k0+kk)*256 + m0 + mm];
            }
        } else {
#pragma unroll
            for (int p = 0; p < 8; ++p){
                int idx = t + p*256;
                int oo = idx >> 5, dd = idx & 31;
                As[dd][oo] = A[(size_t)(m0+oo)*256 + k0 + dd];
            }
        }
#pragma unroll
        for (int p = 0; p < 8; ++p){
            int idx = t + p*256;
            int kk = idx >> 6, nn = idx & 63;
            Bs[kk][nn] = Bm[(size_t)(k0+kk)*256 + n0 + nn];
        }
        __syncthreads();
#pragma unroll
        for (int kk = 0; kk < 32; ++kk){
            float av[4], bw[4];
#pragma unroll
            for (int i = 0; i < 4; ++i){ av[i] = As[kk][ty*4+i]; bw[i] = Bs[kk][tx*4+i]; }
#pragma unroll
            for (int i = 0; i < 4; ++i)
#pragma unroll
                for (int j = 0; j < 4; ++j) acc[i][j] += av[i]*bw[j];
        }
        __syncthreads();
    }
    if (!mode){
#pragma unroll
        for (int i = 0; i < 4; ++i)
#pragma unroll
            for (int j = 0; j < 4; ++j)
                wqkT[(size_t)(n0 + tx*4 + j)*256 + m0 + ty*4 + i] = acc[i][j]*0.0625f;
    } else {
#pragma unroll
        for (int i = 0; i < 4; ++i)
#pragma unroll
            for (int j = 0; j < 4; ++j)
                wf[(size_t)(m0 + ty*4 + i)*256 + n0 + tx*4 + j] = acc[i][j];
    }
}

__global__ __launch_bounds__(256) void fuse_bias_kernel(
        const float* __restrict__ bq,   const float* __restrict__ Wk,
        const float* __restrict__ W_ih, const float* __restrict__ bv,
        const float* __restrict__ b_ih,
        float* __restrict__ bqk, float* __restrict__ bf)
{
    int b = blockIdx.x, t = threadIdx.x;
    if (b == 0){
        float a = 0.f;
#pragma unroll 8
        for (int c = 0; c < 256; ++c) a += bq[c]*__ldg(&Wk[(size_t)c*256 + t]);
        bqk[t] = a * 0.0625f;
    } else {
        int o = (b-1)*256 + t;
        const float4* row = reinterpret_cast<const float4*>(W_ih + (size_t)o*256);
        const float4* vv  = reinterpret_cast<const float4*>(bv);
        float a = 0.f;
#pragma unroll 8
        for (int k4 = 0; k4 < 64; ++k4){
            float4 wv = __ldg(&row[k4]);
            float4 bw = __ldg(&vv[k4]);
            a += wv.x*bw.x + wv.y*bw.y + wv.z*bw.z + wv.w*bw.w;
        }
        bf[o] = a + b_ih[o];
    }
}

// Block LayerNorm (256-thread data path; callable from 256 OR 512 threads).
__device__ __forceinline__ void block_ln4(const float v[4], float o[4],
                                          const float* __restrict__ g,
                                          const float* __restrict__ b, int t)
{
    __shared__ float part[8][4];
    __shared__ float stat[4];
    int w = t >> 5, l = t & 31;
#pragma unroll
    for (int r = 0; r < 4; ++r){
        float p = warpSum(v[r]);
        if (l == 0 && w < 8) part[w][r] = p;
    }
    __syncthreads();
    if (t < 32){
        int rr = l >> 3, ww = l & 7;
        float x = part[ww][rr];
        x += __shfl_xor_sync(0xffffffffu, x, 1);
        x += __shfl_xor_sync(0xffffffffu, x, 2);
        x += __shfl_xor_sync(0xffffffffu, x, 4);
        if (ww == 0) stat[rr] = x * (1.f/256.f);
    }
    __syncthreads();
    float d[4];
#pragma unroll
    for (int r = 0; r < 4; ++r) d[r] = v[r] - stat[r];
    __syncthreads();
#pragma unroll
    for (int r = 0; r < 4; ++r){
        float p = warpSum(d[r]*d[r]);
        if (l == 0 && w < 8) part[w][r] = p;
    }
    __syncthreads();
    if (t < 32){
        int rr = l >> 3, ww = l & 7;
        float x = part[ww][rr];
        x += __shfl_xor_sync(0xffffffffu, x, 1);
        x += __shfl_xor_sync(0xffffffffu, x, 2);
        x += __shfl_xor_sync(0xffffffffu, x, 4);
        if (ww == 0) stat[rr] = rsqrtf(x * (1.f/256.f) + 1e-5f);
    }
    __syncthreads();
    int tc = t & 255;
    float gg = g[tc], bb = b[tc];
#pragma unroll
    for (int r = 0; r < 4; ++r) o[r] = d[r] * stat[r] * gg + bb;
}

// ============ gemm_tiles v2: row-major staging (STS.128 in, LDS.128 out) ============
__device__ __forceinline__ void gemm_tiles(
        const float (*sA)[DD],
        const float* __restrict__ W,
        float* __restrict__ sWt,     // this group's staging [256][36]
        float acc[4], int tc, int ktStart, int ktCount)
{
    const float4* Wp = reinterpret_cast<const float4*>(W);
    float4 r[8];
#pragma unroll
    for (int p = 0; p < 8; ++p){
        int idx = tc + p*256;
        r[p] = __ldg(&Wp[(size_t)(idx >> 3)*64 + ktStart*8 + (idx & 7)]);
    }
    acc[0] = acc[1] = acc[2] = acc[3] = 0.f;

    for (int kt = 0; kt < ktCount; ++kt){
        __syncthreads();
#pragma unroll
        for (int p = 0; p < 8; ++p){
            int idx = tc + p*256;
            *reinterpret_cast<float4*>(&sWt[(idx >> 3)*36 + (idx & 7)*4]) = r[p];
        }
        __syncthreads();
        if (kt + 1 < ktCount){
#pragma unroll
            for (int p = 0; p < 8; ++p){
                int idx = tc + p*256;
                r[p] = __ldg(&Wp[(size_t)(idx >> 3)*64 + (ktStart+kt+1)*8 + (idx & 7)]);
            }
        }
        int kb = (ktStart + kt)*32;
#pragma unroll
        for (int kk4 = 0; kk4 < 8; ++kk4){
            float4 a0 = *(const float4*)&sA[0][kb + kk4*4];
            float4 a1 = *(const float4*)&sA[1][kb + kk4*4];
            float4 a2 = *(const float4*)&sA[2][kb + kk4*4];
            float4 a3 = *(const float4*)&sA[3][kb + kk4*4];
            float4 wv = *(const float4*)&sWt[tc*36 + kk4*4];
            acc[0] += a0.x*wv.x + a0.y*wv.y + a0.z*wv.z + a0.w*wv.w;
            acc[1] += a1.x*wv.x + a1.y*wv.y + a1.z*wv.z + a1.w*wv.w;
            acc[2] += a2.x*wv.x + a2.y*wv.y + a2.z*wv.z + a2.w*wv.w;
            acc[3] += a3.x*wv.x + a3.y*wv.y + a3.z*wv.z + a3.w*wv.w;
        }
    }
}

// ============ PRE (iteration 0 only): LN -> qW = LN @ wqkT^T + bqk ==========
__global__ __launch_bounds__(512) void pre_kernel(
        const float* __restrict__ slots,
        const float* __restrict__ lng, const float* __restrict__ lnb,
        const float* __restrict__ wqkT, const float* __restrict__ bqk,
        float* __restrict__ qW)
{
    extern __shared__ float dsm[];
    float (*s_ln)[DD] = (float(*)[DD])(dsm);            // 1024
    float (*sPar)[DD] = (float(*)[DD])(dsm + 1024);     // 1024
    float* sWtA       = dsm + 2048;                     // 9216
    float* sWtB       = dsm + 11264;                    // 9216

    int r0 = blockIdx.x * 4;
    int t  = threadIdx.x;
    int tc = t & 255, grp = t >> 8;
    float* myWt = grp ? sWtB : sWtA;

    float v[4] = {0.f, 0.f, 0.f, 0.f};
    if (grp == 0){
#pragma unroll
        for (int r = 0; r < 4; ++r) v[r] = slots[(size_t)(r0+r)*DD + tc];
    }
    float o[4];
    block_ln4(v, o, lng, lnb, t);
    if (grp == 0){
#pragma unroll
        for (int r = 0; r < 4; ++r) s_ln[r][tc] = o[r];
    }

    float acc[4];
    gemm_tiles(s_ln, wqkT, myWt, acc, tc, grp*4, 4);
    if (grp == 1){
#pragma unroll
        for (int r = 0; r < 4; ++r) sPar[r][tc] = acc[r];
    }
    __syncthreads();
    if (grp == 0){
        float bb = __ldg(&bqk[tc]);
        qW[(size_t)(r0+0)*IND + tc] = acc[0] + sPar[0][tc] + bb;
        qW[(size_t)(r0+1)*IND + tc] = acc[1] + sPar[1][tc] + bb;
        qW[(size_t)(r0+2)*IND + tc] = acc[2] + sPar[2][tc] + bb;
        qW[(size_t)(r0+3)*IND + tc] = acc[3] + sPar[3][tc] + bb;
    }
}

// ============ FLASH attention, TN=32, f32x2 dual-FMA in phases 1 & 3 ============
__global__ __launch_bounds__(512, 2) void attn_kernel(
        const float* __restrict__ qW,
        const float* __restrict__ inputs,
        float* __restrict__ upart,
        float* __restrict__ mbuf,
        float* __restrict__ lbuf)
{
    extern __shared__ float dsm[];
    float* Xs  = dsm;                  // 2 * 8192 floats (64 KB)
    float* qT  = dsm + 16384;          // [k][s] 2048
    float* lgp = qT  + 2048;           // [ks][s][n] 16*8*32 = 4096
    float* atT = lgp + 4096;           // [n][12] 384
    float* scs = atT + 384;            // 8

    int b = blockIdx.x, g = blockIdx.y;
    int t = threadIdx.x, w = t >> 5, l = t & 31;

    // stage qT
#pragma unroll
    for (int p = 0; p < 4; ++p){
        int idx = t + p*512;
        qT[(idx & 255)*8 + (idx >> 8)] = qW[(size_t)b*2048 + idx];
    }

    const float* src0 = inputs + ((size_t)b*NN + g*(NTILE*TN))*IND;
#define PREFETCH(j, buf) do {                                                   \
        const float* _s = src0 + (size_t)(j)*TN*IND;                            \
        float* _d = Xs + (buf)*8192;                                            \
        _Pragma("unroll")                                                       \
        for (int p = 0; p < 4; ++p){                                            \
            int idx = t + p*512;                                                \
            int n = idx >> 6, k4 = idx & 63;                                    \
            uint32_t sa = (uint32_t)__cvta_generic_to_shared(                   \
                              &_d[(n*64 + (k4 ^ (n & 7)))*4]);                  \
            asm volatile("cp.async.cg.shared.global [%0], [%1], 16;"            \
                         :: "r"(sa), "l"(_s + (size_t)n*IND + k4*4) : "memory");\
        }                                                                       \
        asm volatile("cp.async.commit_group;" ::: "memory");                    \
    } while(0)

    PREFETCH(0, 0);

    float m_run = -3.4e38f, lpart = 0.f;
    unsigned long long u01 = 0ull, u23 = 0ull;   // packed U accumulators (slot pairs)
    const int sh = (t >= 256) ? 4 : 0;     // phase3 slot-half
    const int e  = t & 255;
    const int e4 = e >> 2, eo = e & 3;
    const int ks = t >> 5;                 // phase1 k-slice (= warp id)
    const int pn = t & 31;                 // phase1 n (= lane)

    // ---- hoisted swizzle address math ----
    const int c  = pn & 7;
    const int p1base = pn*256 + ((ks*4) ^ (c & 4))*4;
    int a1[4];
#pragma unroll
    for (int i = 0; i < 4; ++i) a1[i] = p1base + (i ^ (c & 3))*4;
    int off3[8];
#pragma unroll
    for (int cc = 0; cc < 8; ++cc) off3[cc] = (e4 ^ cc)*4 + eo;

    for (int j = 0; j < NTILE; ++j){
        int buf = j & 1;
        asm volatile("cp.async.wait_group 0;" ::: "memory");
        __syncthreads();                                   // S1: tile ready, prior reads done
        if (j + 1 < NTILE) PREFETCH(j + 1, buf ^ 1);
        const float* Xb = Xs + buf*8192;

        // ---- phase 1: logits partials (packed f32x2; slot pairs) ----
        {
            unsigned long long a01 = 0ull, a23 = 0ull, a45 = 0ull, a67 = 0ull;
#pragma unroll
            for (int i = 0; i < 4; ++i){
                float4 x4 = *(const float4*)&Xb[a1[i]];
                int k = (ks*4 + i)*4;
                float xv[4] = {x4.x, x4.y, x4.z, x4.w};
#pragma unroll
                for (int d = 0; d < 4; ++d){
                    unsigned long long xx = f2pack(xv[d]);
                    ulonglong2 qlo = *(const ulonglong2*)&qT[(k+d)*8];
                    ulonglong2 qhi = *(const ulonglong2*)&qT[(k+d)*8 + 4];
                    a01 = fma2(xx, qlo.x, a01);
                    a23 = fma2(xx, qlo.y, a23);
                    a45 = fma2(xx, qhi.x, a45);
                    a67 = fma2(xx, qhi.y, a67);
                }
            }
            float s0,s1,s2,s3,s4,s5,s6,s7;
            unpack2(a01, s0, s1); unpack2(a23, s2, s3);
            unpack2(a45, s4, s5); unpack2(a67, s6, s7);
            lgp[ks*256 + 0*32 + pn] = s0; lgp[ks*256 + 1*32 + pn] = s1;
            lgp[ks*256 + 2*32 + pn] = s2; lgp[ks*256 + 3*32 + pn] = s3;
            lgp[ks*256 + 4*32 + pn] = s4; lgp[ks*256 + 5*32 + pn] = s5;
            lgp[ks*256 + 6*32 + pn] = s6; lgp[ks*256 + 7*32 + pn] = s7;
        }
        __syncthreads();                                   // S2: lgp ready

        // ---- phase 2: online softmax; warp w<8 owns slot w, lane = key ----
        if (w < 8){
            float lg = 0.f;
#pragma unroll
            for (int kq = 0; kq < 16; ++kq) lg += lgp[kq*256 + w*32 + l];
            float mv = warpMax(lg);
            float m_new = fmaxf(m_run, mv);
            float ev = __expf(lg - m_new);
            atT[l*12 + w] = ev;
            float sc = __expf(m_run - m_new);
            lpart = lpart*sc + ev;
            m_run = m_new;
            if (l == 0) scs[w] = sc;
        }
        __syncthreads();                                   // S3: atT/scs ready

        // ---- phase 3: U accumulation (packed f32x2; slot pairs) ----
        {
            ulonglong2 sv2 = *(const ulonglong2*)&scs[sh];
            u01 = mul2(u01, sv2.x);
            u23 = mul2(u23, sv2.y);
            for (int n8 = 0; n8 < TN; n8 += 8){
#pragma unroll
                for (int cc = 0; cc < 8; ++cc){
                    int n = n8 + cc;
                    unsigned long long xx = f2pack(Xb[n*256 + off3[cc]]);
                    ulonglong2 a2 = *(const ulonglong2*)&atT[n*12 + sh];
                    u01 = fma2(xx, a2.x, u01);
                    u23 = fma2(xx, a2.y, u23);
                }
            }
        }
    }
#undef PREFETCH

    {
        float v0,v1,v2,v3;
        unpack2(u01, v0, v1); unpack2(u23, v2, v3);
        size_t base = ((size_t)g*ROWS + b*SS + sh)*IND + e;
        upart[base          ] = v0;
        upart[base +   IND  ] = v1;
        upart[base + 2*IND  ] = v2;
        upart[base + 3*IND  ] = v3;
    }
    if (w < 8){
        float l_run = warpSum(lpart);
        if (l == 0){
            int row = b*SS + w;
            mbuf[(size_t)g*ROWS + row] = m_run;
            lbuf[(size_t)g*ROWS + row] = l_run;
        }
    }
}

// ============ POST: gates -> GRU -> LN -> MLP, plus fused NEXT-ITER qW tail ==========
__global__ __launch_bounds__(512) void post_kernel(
        const float* __restrict__ upart,
        const float* __restrict__ mbuf, const float* __restrict__ lbuf,
        const float* __restrict__ wf,   const float* __restrict__ bf,
        const float* __restrict__ W_hh, const float* __restrict__ b_hh,
        const float* __restrict__ lng,  const float* __restrict__ lnb,
        const float* __restrict__ W1,   const float* __restrict__ b1,
        const float* __restrict__ W2,   const float* __restrict__ b2,
        const float* __restrict__ lnsg, const float* __restrict__ lnsb,
        const float* __restrict__ wqkT, const float* __restrict__ bqk,
        const float* __restrict__ slots_in,
        float* __restrict__ dst,
        float* __restrict__ qW_out)        // null on final iteration
{
    extern __shared__ float dsm[];
    float (*sBufA)[DD] = (float(*)[DD])(dsm);           // 1024  U / sln
    float (*sprev)[DD] = (float(*)[DD])(dsm + 1024);    // 1024
    float (*sBufB)[DD] = (float(*)[DD])(dsm + 2048);    // 1024  hidden
    float* sGh         = dsm + 3072;                    // 3072  gh[3][4][256]
    float (*sPar)[DD]  = (float(*)[DD])(dsm + 6144);    // 1024  split-k partials
    float* sWtA        = dsm + 7168;                    // 9216
    float* sWtB        = dsm + 16384;                   // 9216

    __shared__ float ssc[4][17];
    __shared__ float sinv[4];

    int r0 = blockIdx.x * 4;
    int t  = threadIdx.x;
    int tc = t & 255, grp = t >> 8;
    int w  = t >> 5, l = t & 31;
    float* myWt = grp ? sWtB : sWtA;

    // 1. per-row combine scales over NG=16 groups (warps 0-3, lanes 0-15)
    if (w < 4){
        int row = r0 + w;
        float mv = (l < NG) ? __ldg(&mbuf[(size_t)l*ROWS + row]) : -3.4e38f;
        float mm = mv;
        mm = fmaxf(mm, __shfl_xor_sync(0xffffffffu, mm, 1));
        mm = fmaxf(mm, __shfl_xor_sync(0xffffffffu, mm, 2));
        mm = fmaxf(mm, __shfl_xor_sync(0xffffffffu, mm, 4));
        mm = fmaxf(mm, __shfl_xor_sync(0xffffffffu, mm, 8));
        float e  = (l < NG) ? __expf(mv - mm) : 0.f;
        float lv = (l < NG) ? __ldg(&lbuf[(size_t)l*ROWS + row]) * e : 0.f;
        lv += __shfl_xor_sync(0xffffffffu, lv, 1);
        lv += __shfl_xor_sync(0xffffffffu, lv, 2);
        lv += __shfl_xor_sync(0xffffffffu, lv, 4);
        lv += __shfl_xor_sync(0xffffffffu, lv, 8);
        if (l < NG) ssc[w][l] = e;
        if (l == 0) sinv[w] = 1.f / lv;
    }
    __syncthreads();

    // 2. U = (sum_g Ubar_g*sc_g)*inv ; load slots_prev (each thread 2 rows)
#pragma unroll
    for (int rr = 0; rr < 2; ++rr){
        int r = grp*2 + rr, row = r0 + r;
        float a = 0.f;
#pragma unroll
        for (int ch = 0; ch < NG; ++ch)
            a += __ldg(&upart[((size_t)ch*ROWS + row)*IND + tc]) * ssc[r][ch];
        sBufA[r][tc] = a * sinv[r];
        sprev[r][tc] = slots_in[(size_t)row*DD + tc];
    }
    // (first barrier inside gemm_tiles orders these writes)

    // 3. GRU gates concurrently: grp0 -> gi = U @ wf^T + bf ; grp1 -> gh on prev
    float acc[4];
    float gi[3][4];
#pragma unroll
    for (int j = 0; j < 3; ++j){
        const float* Wg = grp ? (W_hh + (size_t)j*DD*DD) : (wf + (size_t)j*DD*DD);
        const float (*Ag)[DD] = grp ? sprev : sBufA;
        gemm_tiles(Ag, Wg, myWt, acc, tc, 0, 8);
        if (grp == 0){
            float bb = __ldg(&bf[tc + j*256]);
#pragma unroll
            for (int r = 0; r < 4; ++r) gi[j][r] = acc[r] + bb;
        } else {
            float bb = __ldg(&b_hh[tc + j*256]);
#pragma unroll
            for (int r = 0; r < 4; ++r) sGh[(j*4 + r)*256 + tc] = acc[r] + bb;
        }
    }
    __syncthreads();

    // 4. GRU cell + residual (grp0)
    float vnew[4] = {0.f, 0.f, 0.f, 0.f};
    if (grp == 0){
#pragma unroll
        for (int r = 0; r < 4; ++r){
            float hr = sGh[(0*4 + r)*256 + tc];
            float hz = sGh[(1*4 + r)*256 + tc];
            float hn = sGh[(2*4 + r)*256 + tc];
            float rr = 1.f / (1.f + expf(-(gi[0][r] + hr)));
            float zz = 1.f / (1.f + expf(-(gi[1][r] + hz)));
            float nn = tanhf(gi[2][r] + rr*hn);
            float h  = sprev[r][tc];
            vnew[r]  = h + (1.f - zz)*nn + zz*h;
        }
    }

    // 5. LN(vnew) -> sBufA (grp0 data; all threads pass barriers)
    float lnv[4];
    block_ln4(vnew, lnv, lng, lnb, t);
    if (grp == 0){
#pragma unroll
        for (int r = 0; r < 4; ++r) sBufA[r][tc] = lnv[r];
    }

    // 6. hidden = relu(sln @ W1^T + b1) -> sBufB (split-K)
    gemm_tiles(sBufA, W1, myWt, acc, tc, grp*4, 4);
    if (grp == 1){
#pragma unroll
        for (int r = 0; r < 4; ++r) sPar[r][tc] = acc[r];
    }
    __syncthreads();
    if (grp == 0){
        float bb = __ldg(&b1[tc]);
#pragma unroll
        for (int r = 0; r < 4; ++r) sBufB[r][tc] = fmaxf(acc[r] + sPar[r][tc] + bb, 0.f);
    }

    // 7. snew = vnew + hid @ W2^T + b2 (split-K); write dst
    gemm_tiles(sBufB, W2, myWt, acc, tc, grp*4, 4);
    if (grp == 1){
#pragma unroll
        for (int r = 0; r < 4; ++r) sPar[r][tc] = acc[r];
    }
    __syncthreads();
    float snew[4] = {0.f, 0.f, 0.f, 0.f};
    if (grp == 0){
        float bb = __ldg(&b2[tc]);
#pragma unroll
        for (int r = 0; r < 4; ++r){
            snew[r] = vnew[r] + acc[r] + sPar[r][tc] + bb;
            dst[(size_t)(r0+r)*DD + tc] = snew[r];
        }
    }

    // 8. fused next-iteration qW = LN_slots(snew) @ wqkT^T + bqk
    if (qW_out){
        float lnq[4];
        block_ln4(snew, lnq, lnsg, lnsb, t);
        if (grp == 0){
#pragma unroll
            for (int r = 0; r < 4; ++r) sBufA[r][tc] = lnq[r];
        }
        gemm_tiles(sBufA, wqkT, myWt, acc, tc, grp*4, 4);
        if (grp == 1){
#pragma unroll
            for (int r = 0; r < 4; ++r) sPar[r][tc] = acc[r];
        }
        __syncthreads();
        if (grp == 0){
            float bb = __ldg(&bqk[tc]);
#pragma unroll
            for (int r = 0; r < 4; ++r)
                qW_out[(size_t)(r0+r)*IND + tc] = acc[r] + sPar[r][tc] + bb;
        }
    }
}

// ------------------------- host launcher -------------------------
extern "C" void kernel_launch(void* const* d_in, const int* in_sizes, int n_in,
                              void* d_out, int out_size)
{
    const float* inputs = (const float*)d_in[0];
    const float* noise  = (const float*)d_in[1];
    const float* s_mu   = (const float*)d_in[2];
    const float* s_sig  = (const float*)d_in[3];
    const float* Wq = (const float*)d_in[4];  const float* bq = (const float*)d_in[5];
    const float* Wk = (const float*)d_in[6];  /* bk = d_in[7] : dead (softmax shift-invariance) */
    const float* Wv = (const float*)d_in[8];  const float* bv = (const float*)d_in[9];
    const float* W_ih = (const float*)d_in[10]; const float* b_ih = (const float*)d_in[11];
    const float* W_hh = (const float*)d_in[12]; const float* b_hh = (const float*)d_in[13];
    const float* W1 = (const float*)d_in[14]; const float* b1 = (const float*)d_in[15];
    const float* W2 = (const float*)d_in[16]; const float* b2 = (const float*)d_in[17];
    const float* lnsg = (const float*)d_in[18]; const float* lnsb = (const float*)d_in[19];
    const float* lnmg = (const float*)d_in[20]; const float* lnmb = (const float*)d_in[21];
    float* out = (float*)d_out;
    (void)in_sizes; (void)n_in; (void)out_size;

    float *slots, *qW, *upart, *mbuf, *lbuf, *wqkT, *bqk, *wf, *bf;
    cudaGetSymbolAddress((void**)&slots, g_slots);
    cudaGetSymbolAddress((void**)&qW,    g_qW);
    cudaGetSymbolAddress((void**)&upart, g_upart);
    cudaGetSymbolAddress((void**)&mbuf,  g_m);
    cudaGetSymbolAddress((void**)&lbuf,  g_l);
    cudaGetSymbolAddress((void**)&wqkT,  g_wqkT);
    cudaGetSymbolAddress((void**)&bqk,   g_bqk);
    cudaGetSymbolAddress((void**)&wf,    g_wf);
    cudaGetSymbolAddress((void**)&bf,    g_bf);

    const int ATTN_SMEM = (16384 + 2048 + 4096 + 384 + 8) * 4;   // 91,680 B -> 2 blocks/SM
    const int POST_SMEM = (7168 + 9216*2) * 4;                   // 102,400 B
    const int PRE_SMEM  = (2048 + 9216*2) * 4;                   //  81,920 B
    static int s_init = 0;
    if (!s_init){
        cudaFuncSetAttribute(attn_kernel, cudaFuncAttributeMaxDynamicSharedMemorySize, ATTN_SMEM);
        cudaFuncSetAttribute(post_kernel, cudaFuncAttributeMaxDynamicSharedMemorySize, POST_SMEM);
        cudaFuncSetAttribute(pre_kernel,  cudaFuncAttributeMaxDynamicSharedMemorySize, PRE_SMEM);
        s_init = 1;
    }

    dim3 gBN(BB, NG);

    init_slots_kernel<<<ROWS, 256>>>(noise, s_mu, s_sig, slots);
    fuse_gemm_kernel<<<64, 256>>>(Wq, Wk, W_ih, Wv, wqkT, wf);
    fuse_bias_kernel<<<4, 256>>>(bq, Wk, W_ih, bv, b_ih, bqk, bf);

    // iteration 0 computes qW from initial slots; iterations 1,2 get qW from post's tail
    pre_kernel<<<ROWS/4, 512, PRE_SMEM>>>(slots, lnsg, lnsb, wqkT, bqk, qW);

    for (int it = 0; it < 3; ++it){
        attn_kernel<<<gBN, 512, ATTN_SMEM>>>(qW, inputs, upart, mbuf, lbuf);
        float* dst    = (it == 2) ? out : slots;
        float* qWnext = (it == 2) ? nullptr : qW;
        post_kernel<<<ROWS/4, 512, POST_SMEM>>>(upart, mbuf, lbuf, wf, bf, W_hh, b_hh,
                                                lnmg, lnmb, W1, b1, W2, b2,
                                                lnsg, lnsb, wqkT, bqk,
                                                slots, dst, qWnext);
    }
}